// round 1
// baseline (speedup 1.0000x reference)
#include <cuda_runtime.h>
#include <cuda_bf16.h>
#include <cstdint>

#define T_STEPS 512
#define NN 32
#define DD 300
#define RR 3
#define EE 64
#define VGN 40000
#define KFLAT 9600   // NN*DD

// ---------------- scratch (device globals; no allocs allowed) ----------------
__device__ float g_Xg[(size_t)T_STEPS * KFLAT];        // gathered x  [512][9600]
__device__ float g_Upart[(size_t)16 * T_STEPS * DD];   // split-k partials
__device__ float g_U[(size_t)T_STEPS * DD];            // u_t = x_flat @ Wu
__device__ float g_P0[(size_t)T_STEPS * DD];           // proposed row 0 per t
__device__ float g_H[(size_t)T_STEPS * DD];            // relu(new_mem[0]) per t

// ---------------- kernel 1: gather x rows ----------------
__global__ void k_gather(const int* __restrict__ xidx, const float* __restrict__ X) {
    int t = blockIdx.x;
    __shared__ int ids[NN];
    if (threadIdx.x < NN) ids[threadIdx.x] = xidx[t * NN + threadIdx.x];
    __syncthreads();
    for (int i = threadIdx.x; i < KFLAT; i += blockDim.x) {
        int n = i / DD;
        int k = i - n * DD;
        g_Xg[(size_t)t * KFLAT + i] = X[(size_t)ids[n] * DD + k];
    }
}

// ---------------- kernel 2: U = Xg @ Wu, split-k ----------------
#define UT 16    // t per CTA
#define UKS 16   // k splits
#define UK 600   // k per CTA (9600/16)
#define UC 40    // k chunk in smem

__global__ __launch_bounds__(320) void k_ugemm(const float* __restrict__ Wu) {
    int t0 = blockIdx.x * UT;
    int ks = blockIdx.y;
    int kbase = ks * UK;
    int d = threadIdx.x;
    __shared__ float xs[UT][UC];
    float acc[UT];
#pragma unroll
    for (int i = 0; i < UT; i++) acc[i] = 0.f;

    for (int c = 0; c < UK; c += UC) {
        __syncthreads();
        for (int l = threadIdx.x; l < UT * UC; l += blockDim.x) {
            int i = l / UC, j = l - (l / UC) * UC;
            xs[i][j] = g_Xg[(size_t)(t0 + i) * KFLAT + kbase + c + j];
        }
        __syncthreads();
        if (d < DD) {
#pragma unroll 8
            for (int j = 0; j < UC; j++) {
                float w = Wu[(size_t)(kbase + c + j) * DD + d];
#pragma unroll
                for (int i = 0; i < UT; i++) acc[i] += xs[i][j] * w;
            }
        }
    }
    if (d < DD) {
#pragma unroll
        for (int i = 0; i < UT; i++)
            g_Upart[((size_t)ks * T_STEPS + (t0 + i)) * DD + d] = acc[i];
    }
}

__global__ void k_ureduce() {
    int i = blockIdx.x * blockDim.x + threadIdx.x;
    if (i < T_STEPS * DD) {
        float s = 0.f;
#pragma unroll
        for (int p = 0; p < UKS; p++) s += g_Upart[(size_t)p * T_STEPS * DD + i];
        g_U[i] = s;
    }
}

// ---------------- kernel 3: p0_t = conv_t[0] + x0 @ W0 ----------------
__global__ __launch_bounds__(320) void k_p0(const int* __restrict__ esrc,
                                            const int* __restrict__ edst,
                                            const float* __restrict__ convW,
                                            const float* __restrict__ W0) {
    int t = blockIdx.x;
    __shared__ int cnt[RR][NN];
    __shared__ float dinv[RR][NN];
    __shared__ float coef[RR][NN];
    __shared__ float ys[RR + 1][DD];
    int tid = threadIdx.x;

    if (tid < RR * NN) cnt[tid / NN][tid % NN] = 0;
    __syncthreads();

    const int* es = esrc + (size_t)t * RR * EE;
    const int* ed = edst + (size_t)t * RR * EE;
    for (int j = tid; j < RR * EE; j += blockDim.x)
        atomicAdd(&cnt[j / EE][ed[j]], 1);   // integer atomics: deterministic
    __syncthreads();

    if (tid < RR * NN) {
        int r = tid / NN, n = tid % NN;
        dinv[r][n] = rsqrtf((float)(cnt[r][n] + 1));  // deg includes self-loop
        coef[r][n] = 0.f;
    }
    __syncthreads();

    // coefficients for node-0 aggregation; serial per relation => deterministic fp
    if (tid < RR) {
        int r = tid;
        for (int e = 0; e < EE; e++) {
            if (ed[r * EE + e] == 0) {
                int s = es[r * EE + e];
                coef[r][s] += dinv[r][s];
            }
        }
        float d0 = dinv[r][0];
        for (int n = 0; n < NN; n++) coef[r][n] *= d0;
        coef[r][0] += d0 * d0;   // self loop
    }
    __syncthreads();

    const float* xg = g_Xg + (size_t)t * KFLAT;
    for (int k = tid; k < DD; k += blockDim.x) {
        ys[0][k] = xg[k];  // x0 (for W0 term)
#pragma unroll
        for (int r = 0; r < RR; r++) {
            float a = 0.f;
            for (int n = 0; n < NN; n++) {
                float c = coef[r][n];
                if (c != 0.f) a += c * xg[n * DD + k];
            }
            ys[r + 1][k] = a;
        }
    }
    __syncthreads();

    int d = tid;
    if (d < DD) {
        float acc = 0.f;
#pragma unroll 4
        for (int k = 0; k < DD; k++) acc += ys[0][k] * W0[k * DD + d];
#pragma unroll
        for (int r = 0; r < RR; r++) {
            const float* Wr = convW + (size_t)r * DD * DD;
#pragma unroll 4
            for (int k = 0; k < DD; k++) acc += ys[r + 1][k] * Wr[k * DD + d];
        }
        g_P0[(size_t)t * DD + d] = acc;
    }
}

// ---------------- kernel 4: sequential recurrence (single CTA) ----------------
#define KPAD 304
#define NP2 (KPAD / 4)            // 76 quad-rows of k
#define SMEM_C (NP2 * DD * 8 + KPAD * 4 + 608 * 4)

__global__ __launch_bounds__(640, 1) void k_recur(const float* __restrict__ Uu) {
    extern __shared__ char sm[];
    uint2* uub = (uint2*)sm;                                   // [NP2][DD], bf16x4 per entry
    float* m0 = (float*)(sm + (size_t)NP2 * DD * sizeof(uint2)); // [KPAD]
    float* vp = m0 + KPAD;                                     // [608]
    int tid = threadIdx.x;

    // pack Uu -> bf16 quads in smem (Uu fp32 = 360KB doesn't fit; bf16 does)
    for (int i = tid; i < NP2 * DD; i += blockDim.x) {
        int p2 = i / DD, d = i - p2 * DD;
        int k0 = 4 * p2;
        unsigned h[4];
#pragma unroll
        for (int c = 0; c < 4; c++) {
            float v = (k0 + c < DD) ? Uu[(size_t)(k0 + c) * DD + d] : 0.f;
            h[c] = (unsigned)__bfloat16_as_ushort(__float2bfloat16(v));
        }
        uub[i] = make_uint2(h[0] | (h[1] << 16), h[2] | (h[3] << 16));
    }
    for (int i = tid; i < KPAD; i += blockDim.x) m0[i] = 0.f;
    __syncthreads();

    int d = (tid < 600) ? (tid % DD) : 0;
    int pbase = (tid < 600) ? (tid / DD) * (NP2 / 2) : 0;   // k halves
    const uint2* up = uub + (size_t)pbase * DD + d;
    const float4* m4 = (const float4*)m0;

    for (int t = 0; t < T_STEPS; t++) {
        float uval = 0.f, pval = 0.f;
        if (tid < DD) {
            uval = g_U[(size_t)t * DD + tid];
            pval = g_P0[(size_t)t * DD + tid];
        }
        if (tid < 600) {
            float acc = 0.f;
#pragma unroll
            for (int p = 0; p < NP2 / 2; p++) {
                uint2 u = up[(size_t)p * DD];
                float4 m = m4[pbase + p];
                acc += m.x * __uint_as_float(u.x << 16);
                acc += m.y * __uint_as_float(u.x & 0xFFFF0000u);
                acc += m.z * __uint_as_float(u.y << 16);
                acc += m.w * __uint_as_float(u.y & 0xFFFF0000u);
            }
            vp[tid] = acc;
        }
        __syncthreads();
        if (tid < DD) {
            float v = vp[tid] + vp[tid + DD];
            float z = uval + v;
            float g = 1.f / (1.f + __expf(-z));
            float mn = g * pval + (1.f - g) * m0[tid];
            m0[tid] = mn;                       // safe: all GEMV reads done
            g_H[(size_t)t * DD + tid] = fmaxf(mn, 0.f);
        }
        __syncthreads();
    }
}

// ---------------- kernel 5: logits = relu(m0) @ Wg^T + bg (f32x2 GEMM) -------
#define BV 64
#define BT 128
#define BK 20

__global__ __launch_bounds__(256) void k_logits(const float* __restrict__ Wg,
                                                const float* __restrict__ bg,
                                                float* __restrict__ out) {
    __shared__ float wgs[BK][BV];
    __shared__ float hs[BK][BT];
    int v0 = blockIdx.x * BV;
    int t0 = blockIdx.y * BT;
    int tid = threadIdx.x;
    int tv = (tid & 15) * 4;   // 4 v per thread
    int tt = (tid >> 4) * 8;   // 8 t per thread (4 packed pairs)

    unsigned long long acc[4][4];
#pragma unroll
    for (int c = 0; c < 4; c++)
#pragma unroll
        for (int j = 0; j < 4; j++) acc[c][j] = 0ULL;

    for (int kb = 0; kb < DD; kb += BK) {
        __syncthreads();
        for (int l = tid; l < BV * 5; l += 256) {
            int a = l / 5, q = l - (l / 5) * 5;
            float4 w = *(const float4*)&Wg[(size_t)(v0 + a) * DD + kb + q * 4];
            wgs[q * 4 + 0][a] = w.x; wgs[q * 4 + 1][a] = w.y;
            wgs[q * 4 + 2][a] = w.z; wgs[q * 4 + 3][a] = w.w;
        }
        for (int l = tid; l < BT * 5; l += 256) {
            int i = l / 5, q = l - (l / 5) * 5;
            float4 h = *(const float4*)&g_H[(size_t)(t0 + i) * DD + kb + q * 4];
            hs[q * 4 + 0][i] = h.x; hs[q * 4 + 1][i] = h.y;
            hs[q * 4 + 2][i] = h.z; hs[q * 4 + 3][i] = h.w;
        }
        __syncthreads();
#pragma unroll
        for (int k = 0; k < BK; k++) {
            unsigned long long hp[4];
#pragma unroll
            for (int j = 0; j < 4; j++)
                hp[j] = *(const unsigned long long*)&hs[k][tt + 2 * j];
#pragma unroll
            for (int c = 0; c < 4; c++) {
                float w = wgs[k][tv + c];
                unsigned long long wp;
                asm("mov.b64 %0, {%1, %1};" : "=l"(wp) : "f"(w));
#pragma unroll
                for (int j = 0; j < 4; j++)
                    asm("fma.rn.f32x2 %0, %1, %2, %0;"
                        : "+l"(acc[c][j]) : "l"(hp[j]), "l"(wp));
            }
        }
    }
#pragma unroll
    for (int c = 0; c < 4; c++) {
        int v = v0 + tv + c;
        float b = bg[v];
#pragma unroll
        for (int j = 0; j < 4; j++) {
            float lo = __uint_as_float((unsigned)(acc[c][j] & 0xFFFFFFFFULL));
            float hi = __uint_as_float((unsigned)(acc[c][j] >> 32));
            int t = t0 + tt + 2 * j;
            out[(size_t)t * VGN + v] = lo + b;
            out[(size_t)(t + 1) * VGN + v] = hi + b;
        }
    }
}

// ---------------- kernel 6: in-place log_softmax per row ----------------
__global__ __launch_bounds__(512) void k_logsoftmax(float* __restrict__ out) {
    int t = blockIdx.x;
    float* row = out + (size_t)t * VGN;
    __shared__ float red[32];
    int tid = threadIdx.x;

    float m = -1e30f;
    for (int v = tid; v < VGN; v += blockDim.x) m = fmaxf(m, row[v]);
#pragma unroll
    for (int o = 16; o; o >>= 1) m = fmaxf(m, __shfl_xor_sync(~0u, m, o));
    if ((tid & 31) == 0) red[tid >> 5] = m;
    __syncthreads();
    if (tid < 32) {
        float x = (tid < (int)(blockDim.x >> 5)) ? red[tid] : -1e30f;
#pragma unroll
        for (int o = 16; o; o >>= 1) x = fmaxf(x, __shfl_xor_sync(~0u, x, o));
        if (tid == 0) red[0] = x;
    }
    __syncthreads();
    m = red[0];
    __syncthreads();

    float s = 0.f;
    for (int v = tid; v < VGN; v += blockDim.x) s += __expf(row[v] - m);
#pragma unroll
    for (int o = 16; o; o >>= 1) s += __shfl_xor_sync(~0u, s, o);
    if ((tid & 31) == 0) red[tid >> 5] = s;
    __syncthreads();
    if (tid < 32) {
        float x = (tid < (int)(blockDim.x >> 5)) ? red[tid] : 0.f;
#pragma unroll
        for (int o = 16; o; o >>= 1) x += __shfl_xor_sync(~0u, x, o);
        if (tid == 0) red[0] = x;
    }
    __syncthreads();
    float lse = m + logf(red[0]);
    for (int v = tid; v < VGN; v += blockDim.x) row[v] -= lse;
}

// ---------------- tail zero (second ref output = zeros) ----------------
__global__ void k_zero(float* out, size_t start, size_t n) {
    size_t i = (size_t)blockIdx.x * blockDim.x + threadIdx.x;
    if (i < n) out[start + i] = 0.f;
}

extern "C" void kernel_launch(void* const* d_in, const int* in_sizes, int n_in,
                              void* d_out, int out_size) {
    const int*   xidx  = (const int*)d_in[0];
    const int*   esrc  = (const int*)d_in[1];
    const int*   edst  = (const int*)d_in[2];
    const float* X     = (const float*)d_in[3];
    const float* convW = (const float*)d_in[4];
    const float* W0    = (const float*)d_in[5];
    const float* Wu    = (const float*)d_in[6];
    const float* Uu    = (const float*)d_in[7];
    const float* Wg    = (const float*)d_in[8];
    const float* bg    = (const float*)d_in[9];
    float* out = (float*)d_out;

    cudaFuncSetAttribute(k_recur, cudaFuncAttributeMaxDynamicSharedMemorySize, SMEM_C);

    k_gather<<<T_STEPS, 256>>>(xidx, X);
    k_ugemm<<<dim3(T_STEPS / UT, UKS), 320>>>(Wu);
    k_ureduce<<<(T_STEPS * DD + 255) / 256, 256>>>();
    k_p0<<<T_STEPS, 320>>>(esrc, edst, convW, W0);
    k_recur<<<1, 640, SMEM_C>>>(Uu);
    k_logits<<<dim3(VGN / BV, T_STEPS / BT), 256>>>(Wg, bg, out);
    k_logsoftmax<<<T_STEPS, 512>>>(out);

    size_t used = (size_t)T_STEPS * VGN;
    if ((size_t)out_size > used) {
        size_t n = (size_t)out_size - used;
        k_zero<<<(unsigned)((n + 255) / 256), 256>>>(out, used, n);
    }
}

// round 2
// speedup vs baseline: 1.4488x; 1.4488x over previous
#include <cuda_runtime.h>
#include <cuda_bf16.h>
#include <cstdint>

#define T_STEPS 512
#define NN 32
#define DD 300
#define RR 3
#define EE 64
#define VGN 40000
#define KFLAT 9600   // NN*DD
#define TD (T_STEPS * DD)

// ---------------- scratch (device globals; no allocs allowed) ----------------
__device__ float g_Xg[(size_t)T_STEPS * KFLAT];        // gathered x  [512][9600]
__device__ float g_Upart[(size_t)16 * TD];             // U split-k partials
__device__ float g_Ppart[(size_t)4 * TD];              // P0 split-s partials
__device__ float g_Y[(size_t)T_STEPS * 4 * DD];        // aggregated rows per (t,s)
__device__ float g_U[(size_t)TD];                      // u_t = x_flat @ Wu
__device__ float g_P0[(size_t)TD];                     // proposed row 0 per t
__device__ float g_H[(size_t)TD];                      // relu(new_mem[0]) per t

// ---------------- kernel 1: gather x rows ----------------
__global__ void k_gather(const int* __restrict__ xidx, const float* __restrict__ X) {
    int t = blockIdx.x;
    __shared__ int ids[NN];
    if (threadIdx.x < NN) ids[threadIdx.x] = xidx[t * NN + threadIdx.x];
    __syncthreads();
    for (int i = threadIdx.x; i < KFLAT; i += blockDim.x) {
        int n = i / DD;
        int k = i - n * DD;
        g_Xg[(size_t)t * KFLAT + i] = X[(size_t)ids[n] * DD + k];
    }
}

// ---------------- kernel 2: U = Xg @ Wu, split-k ----------------
#define UT 16    // t per CTA
#define UKS 16   // k splits
#define UK 600   // k per CTA (9600/16)
#define UC 40    // k chunk in smem

__global__ __launch_bounds__(320) void k_ugemm(const float* __restrict__ Wu) {
    int t0 = blockIdx.x * UT;
    int ks = blockIdx.y;
    int kbase = ks * UK;
    int d = threadIdx.x;
    __shared__ float xs[UT][UC];
    float acc[UT];
#pragma unroll
    for (int i = 0; i < UT; i++) acc[i] = 0.f;

    for (int c = 0; c < UK; c += UC) {
        __syncthreads();
        for (int l = threadIdx.x; l < UT * UC; l += blockDim.x) {
            int i = l / UC, j = l - (l / UC) * UC;
            xs[i][j] = g_Xg[(size_t)(t0 + i) * KFLAT + kbase + c + j];
        }
        __syncthreads();
        if (d < DD) {
#pragma unroll 8
            for (int j = 0; j < UC; j++) {
                float w = Wu[(size_t)(kbase + c + j) * DD + d];
#pragma unroll
                for (int i = 0; i < UT; i++) acc[i] += xs[i][j] * w;
            }
        }
    }
    if (d < DD) {
#pragma unroll
        for (int i = 0; i < UT; i++)
            g_Upart[((size_t)ks * T_STEPS + (t0 + i)) * DD + d] = acc[i];
    }
}

// ---------------- kernel 3a: per-t coefficients + aggregated rows Y ----------
__global__ __launch_bounds__(128) void k_coefY(const int* __restrict__ esrc,
                                               const int* __restrict__ edst) {
    int t = blockIdx.x;
    int tid = threadIdx.x;
    __shared__ int cnt[RR][NN];
    __shared__ float dinv[RR][NN];
    __shared__ float cval[RR][NN + 1];
    __shared__ int cidx[RR][NN + 1];
    __shared__ int cn[RR];

    if (tid < RR * NN) cnt[tid / NN][tid % NN] = 0;
    __syncthreads();

    const int* es = esrc + (size_t)t * RR * EE;
    const int* ed = edst + (size_t)t * RR * EE;
    for (int j = tid; j < RR * EE; j += 128)
        atomicAdd(&cnt[j / EE][ed[j]], 1);   // integer atomics: deterministic
    __syncthreads();

    if (tid < RR * NN) {
        int r = tid / NN, n = tid % NN;
        dinv[r][n] = rsqrtf((float)(cnt[r][n] + 1));  // deg includes self-loop
    }
    __syncthreads();

    if (tid < RR) {
        int r = tid;
        float c[NN];
#pragma unroll
        for (int n = 0; n < NN; n++) c[n] = 0.f;
        for (int e = 0; e < EE; e++) {
            if (ed[r * EE + e] == 0) {
                int s = es[r * EE + e];
                c[s] += dinv[r][s];
            }
        }
        float d0 = dinv[r][0];
        c[0] += d0;               // self loop: (c0 + d0)*d0 == c0*d0 + d0^2
        int m = 0;
        for (int n = 0; n < NN; n++) {
            if (c[n] != 0.f) { cidx[r][m] = n; cval[r][m] = c[n] * d0; m++; }
        }
        cn[r] = m;
    }
    __syncthreads();

    const float* xg = g_Xg + (size_t)t * KFLAT;
    float* Yt = g_Y + (size_t)t * 4 * DD;
    for (int k = tid; k < DD; k += 128) {
        Yt[k] = xg[k];   // s=0: x0 (for W0 term)
#pragma unroll
        for (int r = 0; r < RR; r++) {
            float a = 0.f;
            int m = cn[r];
            for (int q = 0; q < m; q++)
                a += cval[r][q] * xg[cidx[r][q] * DD + k];
            Yt[(r + 1) * DD + k] = a;
        }
    }
}

// ---------------- kernel 3b: P0 partials = Y[:,s,:] @ Ws ----------------
#define PT 8

__global__ __launch_bounds__(320) void k_pgemm(const float* __restrict__ convW,
                                               const float* __restrict__ W0) {
    int t0 = blockIdx.x * PT;
    int s = blockIdx.y;
    const float* W = (s == 0) ? W0 : (convW + (size_t)(s - 1) * DD * DD);
    int d = threadIdx.x;
    __shared__ float ys[PT][60];
    float acc[PT];
#pragma unroll
    for (int i = 0; i < PT; i++) acc[i] = 0.f;

    for (int c = 0; c < DD; c += 60) {
        __syncthreads();
        for (int l = threadIdx.x; l < PT * 60; l += 320) {
            int i = l / 60, j = l - (l / 60) * 60;
            ys[i][j] = g_Y[((size_t)(t0 + i) * 4 + s) * DD + c + j];
        }
        __syncthreads();
        if (d < DD) {
#pragma unroll 10
            for (int j = 0; j < 60; j++) {
                float w = W[(size_t)(c + j) * DD + d];
#pragma unroll
                for (int i = 0; i < PT; i++) acc[i] += ys[i][j] * w;
            }
        }
    }
    if (d < DD) {
#pragma unroll
        for (int i = 0; i < PT; i++)
            g_Ppart[((size_t)s * T_STEPS + t0 + i) * DD + d] = acc[i];
    }
}

// ---------------- kernel 3c: reduce U (16) and P0 (4) partials ----------------
__global__ void k_reduce2() {
    int i = blockIdx.x * blockDim.x + threadIdx.x;
    if (i < TD) {
        float s = 0.f;
#pragma unroll
        for (int p = 0; p < UKS; p++) s += g_Upart[(size_t)p * TD + i];
        g_U[i] = s;
        float q = 0.f;
#pragma unroll
        for (int p = 0; p < 4; p++) q += g_Ppart[(size_t)p * TD + i];
        g_P0[i] = q;
    }
}

// ---------------- kernel 4: sequential recurrence (single CTA) ----------------
// 600 active threads = 75 d-quads x 8 k-chunks. Each thread: 4 d's, 38 k's.
// k's [0,16): fp32 pairs in registers (64 regs). k's [16,38): bf16x4 in smem.
// m0 kept duplicated {m,m} in smem so fma.rn.f32x2 consumes LDS.64 directly.
#define RT 640
#define JT 38
#define JR 16
#define JS (JT - JR)          // 22
#define KPAD 304
#define OFF_SW 0
#define OFF_M  (JS * RT * 8)                 // 112640 (16B aligned)
#define OFF_VP (OFF_M + 2 * KPAD * 4)        // +2432
#define SMEM_R (OFF_VP + 8 * KPAD * 4)       // +9728 = 124800 bytes

__device__ __forceinline__ void fma2(unsigned long long& acc,
                                     unsigned long long a,
                                     unsigned long long b) {
    asm("fma.rn.f32x2 %0, %1, %2, %0;" : "+l"(acc) : "l"(a), "l"(b));
}
__device__ __forceinline__ unsigned long long pk64(unsigned a, unsigned b) {
    unsigned long long r;
    asm("mov.b64 %0, {%1, %2};" : "=l"(r) : "r"(a), "r"(b));
    return r;
}

__global__ void __launch_bounds__(RT, 1) k_recur(const float* __restrict__ Uu) {
    extern __shared__ char sm[];
    uint2* sw = (uint2*)(sm + OFF_SW);           // [JS][RT]
    float* m0dup = (float*)(sm + OFF_M);         // [2*KPAD], {m,m} per k
    float* vpf = (float*)(sm + OFF_VP);          // [8][KPAD]
    int tid = threadIdx.x;
    int kc = tid / 80;
    int dq = tid - kc * 80;
    bool act = (dq < 75);
    int k0 = kc * JT;
    int d0 = dq * 4;

    // ---- prologue: weights into regs (fp32 pairs) and smem (bf16x4) ----
    unsigned long long wr[JR][2];
    if (act) {
#pragma unroll
        for (int j = 0; j < JR; j++) {
            int k = k0 + j;
            float4 w = (k < DD) ? *(const float4*)&Uu[(size_t)k * DD + d0]
                                : make_float4(0.f, 0.f, 0.f, 0.f);
            wr[j][0] = pk64(__float_as_uint(w.x), __float_as_uint(w.y));
            wr[j][1] = pk64(__float_as_uint(w.z), __float_as_uint(w.w));
        }
#pragma unroll
        for (int j = JR; j < JT; j++) {
            int k = k0 + j;
            float4 w = (k < DD) ? *(const float4*)&Uu[(size_t)k * DD + d0]
                                : make_float4(0.f, 0.f, 0.f, 0.f);
            unsigned a = (unsigned)__bfloat16_as_ushort(__float2bfloat16(w.x)) |
                         ((unsigned)__bfloat16_as_ushort(__float2bfloat16(w.y)) << 16);
            unsigned b = (unsigned)__bfloat16_as_ushort(__float2bfloat16(w.z)) |
                         ((unsigned)__bfloat16_as_ushort(__float2bfloat16(w.w)) << 16);
            sw[(size_t)(j - JR) * RT + tid] = make_uint2(a, b);
        }
    }
    for (int i = tid; i < 2 * KPAD; i += RT) m0dup[i] = 0.f;
    __syncthreads();

    const ulonglong2* mp = (const ulonglong2*)&m0dup[2 * k0];  // 16B aligned

    for (int t = 0; t < T_STEPS; t++) {
        float uval = 0.f, pval = 0.f, mold = 0.f;
        if (tid < DD) {
            uval = g_U[(size_t)t * DD + tid];
            pval = g_P0[(size_t)t * DD + tid];
            mold = m0dup[2 * tid];
        }
        if (act) {
            unsigned long long acc0 = 0ULL, acc1 = 0ULL;
#pragma unroll
            for (int j = 0; j < JR; j += 2) {
                ulonglong2 mm = mp[j >> 1];     // {m_k,m_k},{m_k1,m_k1}
                fma2(acc0, wr[j][0], mm.x);
                fma2(acc1, wr[j][1], mm.x);
                fma2(acc0, wr[j + 1][0], mm.y);
                fma2(acc1, wr[j + 1][1], mm.y);
            }
#pragma unroll
            for (int j = JR; j < JT; j += 2) {
                ulonglong2 mm = mp[j >> 1];
                uint2 wa = sw[(size_t)(j - JR) * RT + tid];
                uint2 wb = sw[(size_t)(j - JR + 1) * RT + tid];
                fma2(acc0, pk64(wa.x << 16, wa.x & 0xFFFF0000u), mm.x);
                fma2(acc1, pk64(wa.y << 16, wa.y & 0xFFFF0000u), mm.x);
                fma2(acc0, pk64(wb.x << 16, wb.x & 0xFFFF0000u), mm.y);
                fma2(acc1, pk64(wb.y << 16, wb.y & 0xFFFF0000u), mm.y);
            }
            *(unsigned long long*)&vpf[kc * KPAD + d0] = acc0;      // {v_d0,v_d1}
            *(unsigned long long*)&vpf[kc * KPAD + d0 + 2] = acc1;  // {v_d2,v_d3}
        }
        __syncthreads();
        if (tid < DD) {
            float v = 0.f;
#pragma unroll
            for (int c = 0; c < 8; c++) v += vpf[c * KPAD + tid];
            float z = uval + v;
            float g = 1.f / (1.f + __expf(-z));
            float mn = mold + g * (pval - mold);
            m0dup[2 * tid] = mn;
            m0dup[2 * tid + 1] = mn;
            g_H[(size_t)t * DD + tid] = fmaxf(mn, 0.f);
        }
        __syncthreads();
    }
}

// ---------------- kernel 5: logits = relu(m0) @ Wg^T + bg (f32x2 GEMM) -------
#define BV 64
#define BT 128
#define BK 20

__global__ __launch_bounds__(256) void k_logits(const float* __restrict__ Wg,
                                                const float* __restrict__ bg,
                                                float* __restrict__ out) {
    __shared__ float wgs[BK][BV];
    __shared__ float hs[BK][BT];
    int v0 = blockIdx.x * BV;
    int t0 = blockIdx.y * BT;
    int tid = threadIdx.x;
    int tv = (tid & 15) * 4;   // 4 v per thread
    int tt = (tid >> 4) * 8;   // 8 t per thread (4 packed pairs)

    unsigned long long acc[4][4];
#pragma unroll
    for (int c = 0; c < 4; c++)
#pragma unroll
        for (int j = 0; j < 4; j++) acc[c][j] = 0ULL;

    for (int kb = 0; kb < DD; kb += BK) {
        __syncthreads();
        for (int l = tid; l < BV * 5; l += 256) {
            int a = l / 5, q = l - (l / 5) * 5;
            float4 w = *(const float4*)&Wg[(size_t)(v0 + a) * DD + kb + q * 4];
            wgs[q * 4 + 0][a] = w.x; wgs[q * 4 + 1][a] = w.y;
            wgs[q * 4 + 2][a] = w.z; wgs[q * 4 + 3][a] = w.w;
        }
        for (int l = tid; l < BT * 5; l += 256) {
            int i = l / 5, q = l - (l / 5) * 5;
            float4 h = *(const float4*)&g_H[(size_t)(t0 + i) * DD + kb + q * 4];
            hs[q * 4 + 0][i] = h.x; hs[q * 4 + 1][i] = h.y;
            hs[q * 4 + 2][i] = h.z; hs[q * 4 + 3][i] = h.w;
        }
        __syncthreads();
#pragma unroll
        for (int k = 0; k < BK; k++) {
            unsigned long long hp[4];
#pragma unroll
            for (int j = 0; j < 4; j++)
                hp[j] = *(const unsigned long long*)&hs[k][tt + 2 * j];
#pragma unroll
            for (int c = 0; c < 4; c++) {
                float w = wgs[k][tv + c];
                unsigned long long wp;
                asm("mov.b64 %0, {%1, %1};" : "=l"(wp) : "f"(w));
#pragma unroll
                for (int j = 0; j < 4; j++)
                    asm("fma.rn.f32x2 %0, %1, %2, %0;"
                        : "+l"(acc[c][j]) : "l"(hp[j]), "l"(wp));
            }
        }
    }
#pragma unroll
    for (int c = 0; c < 4; c++) {
        int v = v0 + tv + c;
        float b = bg[v];
#pragma unroll
        for (int j = 0; j < 4; j++) {
            float lo = __uint_as_float((unsigned)(acc[c][j] & 0xFFFFFFFFULL));
            float hi = __uint_as_float((unsigned)(acc[c][j] >> 32));
            int t = t0 + tt + 2 * j;
            out[(size_t)t * VGN + v] = lo + b;
            out[(size_t)(t + 1) * VGN + v] = hi + b;
        }
    }
}

// ---------------- kernel 6: in-place log_softmax per row ----------------
__global__ __launch_bounds__(512) void k_logsoftmax(float* __restrict__ out) {
    int t = blockIdx.x;
    float* row = out + (size_t)t * VGN;
    __shared__ float red[32];
    int tid = threadIdx.x;

    float m = -1e30f;
    for (int v = tid; v < VGN; v += blockDim.x) m = fmaxf(m, row[v]);
#pragma unroll
    for (int o = 16; o; o >>= 1) m = fmaxf(m, __shfl_xor_sync(~0u, m, o));
    if ((tid & 31) == 0) red[tid >> 5] = m;
    __syncthreads();
    if (tid < 32) {
        float x = (tid < (int)(blockDim.x >> 5)) ? red[tid] : -1e30f;
#pragma unroll
        for (int o = 16; o; o >>= 1) x = fmaxf(x, __shfl_xor_sync(~0u, x, o));
        if (tid == 0) red[0] = x;
    }
    __syncthreads();
    m = red[0];
    __syncthreads();

    float s = 0.f;
    for (int v = tid; v < VGN; v += blockDim.x) s += __expf(row[v] - m);
#pragma unroll
    for (int o = 16; o; o >>= 1) s += __shfl_xor_sync(~0u, s, o);
    if ((tid & 31) == 0) red[tid >> 5] = s;
    __syncthreads();
    if (tid < 32) {
        float x = (tid < (int)(blockDim.x >> 5)) ? red[tid] : 0.f;
#pragma unroll
        for (int o = 16; o; o >>= 1) x += __shfl_xor_sync(~0u, x, o);
        if (tid == 0) red[0] = x;
    }
    __syncthreads();
    float lse = m + logf(red[0]);
    for (int v = tid; v < VGN; v += blockDim.x) row[v] -= lse;
}

// ---------------- tail zero (second ref output = zeros) ----------------
__global__ void k_zero(float* out, size_t start, size_t n) {
    size_t i = (size_t)blockIdx.x * blockDim.x + threadIdx.x;
    if (i < n) out[start + i] = 0.f;
}

extern "C" void kernel_launch(void* const* d_in, const int* in_sizes, int n_in,
                              void* d_out, int out_size) {
    const int*   xidx  = (const int*)d_in[0];
    const int*   esrc  = (const int*)d_in[1];
    const int*   edst  = (const int*)d_in[2];
    const float* X     = (const float*)d_in[3];
    const float* convW = (const float*)d_in[4];
    const float* W0    = (const float*)d_in[5];
    const float* Wu    = (const float*)d_in[6];
    const float* Uu    = (const float*)d_in[7];
    const float* Wg    = (const float*)d_in[8];
    const float* bg    = (const float*)d_in[9];
    float* out = (float*)d_out;

    cudaFuncSetAttribute(k_recur, cudaFuncAttributeMaxDynamicSharedMemorySize, SMEM_R);

    k_gather<<<T_STEPS, 256>>>(xidx, X);
    k_ugemm<<<dim3(T_STEPS / UT, UKS), 320>>>(Wu);
    k_coefY<<<T_STEPS, 128>>>(esrc, edst);
    k_pgemm<<<dim3(T_STEPS / PT, 4), 320>>>(convW, W0);
    k_reduce2<<<(TD + 255) / 256, 256>>>();
    k_recur<<<1, RT, SMEM_R>>>(Uu);
    k_logits<<<dim3(VGN / BV, T_STEPS / BT), 256>>>(Wg, bg, out);
    k_logsoftmax<<<T_STEPS, 512>>>(out);

    size_t used = (size_t)T_STEPS * VGN;
    if ((size_t)out_size > used) {
        size_t n = (size_t)out_size - used;
        k_zero<<<(unsigned)((n + 255) / 256), 256>>>(out, used, n);
    }
}

// round 3
// speedup vs baseline: 1.4564x; 1.0053x over previous
#include <cuda_runtime.h>
#include <cuda_bf16.h>
#include <cstdint>

#define T_STEPS 512
#define NN 32
#define DD 300
#define RR 3
#define EE 64
#define VGN 40000
#define KFLAT 9600   // NN*DD
#define TD (T_STEPS * DD)

// ---------------- scratch (device globals; no allocs allowed) ----------------
__device__ float g_Xg[(size_t)T_STEPS * KFLAT];        // gathered x  [512][9600]
__device__ float g_Upart[(size_t)16 * TD];             // U split-k partials
__device__ float g_Ppart[(size_t)4 * TD];              // P0 split-s partials
__device__ float g_Y[(size_t)T_STEPS * 4 * DD];        // aggregated rows per (t,s)
__device__ float g_U[(size_t)TD];                      // u_t = x_flat @ Wu
__device__ float g_P0[(size_t)TD];                     // proposed row 0 per t
__device__ float g_H[(size_t)TD];                      // relu(new_mem[0]) per t

// ---------------- kernel 1: gather x rows ----------------
__global__ void k_gather(const int* __restrict__ xidx, const float* __restrict__ X) {
    int t = blockIdx.x;
    __shared__ int ids[NN];
    if (threadIdx.x < NN) ids[threadIdx.x] = xidx[t * NN + threadIdx.x];
    __syncthreads();
    for (int i = threadIdx.x; i < KFLAT; i += blockDim.x) {
        int n = i / DD;
        int k = i - n * DD;
        g_Xg[(size_t)t * KFLAT + i] = X[(size_t)ids[n] * DD + k];
    }
}

// ---------------- kernel 2: U = Xg @ Wu, split-k ----------------
#define UT 16    // t per CTA
#define UKS 16   // k splits
#define UK 600   // k per CTA (9600/16)
#define UC 40    // k chunk in smem

__global__ __launch_bounds__(320) void k_ugemm(const float* __restrict__ Wu) {
    int t0 = blockIdx.x * UT;
    int ks = blockIdx.y;
    int kbase = ks * UK;
    int d = threadIdx.x;
    __shared__ float xs[UT][UC];
    float acc[UT];
#pragma unroll
    for (int i = 0; i < UT; i++) acc[i] = 0.f;

    for (int c = 0; c < UK; c += UC) {
        __syncthreads();
        for (int l = threadIdx.x; l < UT * UC; l += blockDim.x) {
            int i = l / UC, j = l - (l / UC) * UC;
            xs[i][j] = g_Xg[(size_t)(t0 + i) * KFLAT + kbase + c + j];
        }
        __syncthreads();
        if (d < DD) {
#pragma unroll 8
            for (int j = 0; j < UC; j++) {
                float w = Wu[(size_t)(kbase + c + j) * DD + d];
#pragma unroll
                for (int i = 0; i < UT; i++) acc[i] += xs[i][j] * w;
            }
        }
    }
    if (d < DD) {
#pragma unroll
        for (int i = 0; i < UT; i++)
            g_Upart[((size_t)ks * T_STEPS + (t0 + i)) * DD + d] = acc[i];
    }
}

// ---------------- kernel 3a: per-t coefficients + aggregated rows Y ----------
__global__ __launch_bounds__(128) void k_coefY(const int* __restrict__ esrc,
                                               const int* __restrict__ edst) {
    int t = blockIdx.x;
    int tid = threadIdx.x;
    __shared__ int cnt[RR][NN];
    __shared__ float dinv[RR][NN];
    __shared__ float cval[RR][NN + 1];
    __shared__ int cidx[RR][NN + 1];
    __shared__ int cn[RR];

    if (tid < RR * NN) cnt[tid / NN][tid % NN] = 0;
    __syncthreads();

    const int* es = esrc + (size_t)t * RR * EE;
    const int* ed = edst + (size_t)t * RR * EE;
    for (int j = tid; j < RR * EE; j += 128)
        atomicAdd(&cnt[j / EE][ed[j]], 1);   // integer atomics: deterministic
    __syncthreads();

    if (tid < RR * NN) {
        int r = tid / NN, n = tid % NN;
        dinv[r][n] = rsqrtf((float)(cnt[r][n] + 1));  // deg includes self-loop
    }
    __syncthreads();

    if (tid < RR) {
        int r = tid;
        float c[NN];
#pragma unroll
        for (int n = 0; n < NN; n++) c[n] = 0.f;
        for (int e = 0; e < EE; e++) {
            if (ed[r * EE + e] == 0) {
                int s = es[r * EE + e];
                c[s] += dinv[r][s];
            }
        }
        float d0 = dinv[r][0];
        c[0] += d0;               // self loop: (c0 + d0)*d0 == c0*d0 + d0^2
        int m = 0;
        for (int n = 0; n < NN; n++) {
            if (c[n] != 0.f) { cidx[r][m] = n; cval[r][m] = c[n] * d0; m++; }
        }
        cn[r] = m;
    }
    __syncthreads();

    const float* xg = g_Xg + (size_t)t * KFLAT;
    float* Yt = g_Y + (size_t)t * 4 * DD;
    for (int k = tid; k < DD; k += 128) {
        Yt[k] = xg[k];   // s=0: x0 (for W0 term)
#pragma unroll
        for (int r = 0; r < RR; r++) {
            float a = 0.f;
            int m = cn[r];
            for (int q = 0; q < m; q++)
                a += cval[r][q] * xg[cidx[r][q] * DD + k];
            Yt[(r + 1) * DD + k] = a;
        }
    }
}

// ---------------- kernel 3b: P0 partials = Y[:,s,:] @ Ws ----------------
#define PT 8

__global__ __launch_bounds__(320) void k_pgemm(const float* __restrict__ convW,
                                               const float* __restrict__ W0) {
    int t0 = blockIdx.x * PT;
    int s = blockIdx.y;
    const float* W = (s == 0) ? W0 : (convW + (size_t)(s - 1) * DD * DD);
    int d = threadIdx.x;
    __shared__ float ys[PT][60];
    float acc[PT];
#pragma unroll
    for (int i = 0; i < PT; i++) acc[i] = 0.f;

    for (int c = 0; c < DD; c += 60) {
        __syncthreads();
        for (int l = threadIdx.x; l < PT * 60; l += 320) {
            int i = l / 60, j = l - (l / 60) * 60;
            ys[i][j] = g_Y[((size_t)(t0 + i) * 4 + s) * DD + c + j];
        }
        __syncthreads();
        if (d < DD) {
#pragma unroll 10
            for (int j = 0; j < 60; j++) {
                float w = W[(size_t)(c + j) * DD + d];
#pragma unroll
                for (int i = 0; i < PT; i++) acc[i] += ys[i][j] * w;
            }
        }
    }
    if (d < DD) {
#pragma unroll
        for (int i = 0; i < PT; i++)
            g_Ppart[((size_t)s * T_STEPS + t0 + i) * DD + d] = acc[i];
    }
}

// ---------------- kernel 3c: reduce U (16) and P0 (4) partials ----------------
__global__ void k_reduce2() {
    int i = blockIdx.x * blockDim.x + threadIdx.x;
    if (i < TD) {
        float s = 0.f;
#pragma unroll
        for (int p = 0; p < UKS; p++) s += g_Upart[(size_t)p * TD + i];
        g_U[i] = s;
        float q = 0.f;
#pragma unroll
        for (int p = 0; p < 4; p++) q += g_Ppart[(size_t)p * TD + i];
        g_P0[i] = q;
    }
}

// ---------------- kernel 4: sequential recurrence (single CTA) ----------------
// 600 active threads = 75 d-quads x 8 k-chunks. Each thread: 4 d's, 38 k's.
// k's [0,16): fp32 pairs in registers (64 regs). k's [16,38): bf16x4 in smem.
// m0 kept duplicated {m,m} in smem so fma.rn.f32x2 consumes LDS.64 directly.
#define RT 640
#define JT 38
#define JR 16
#define JS (JT - JR)          // 22
#define KPAD 304
#define OFF_SW 0
#define OFF_M  (JS * RT * 8)                 // 112640 (16B aligned)
#define OFF_VP (OFF_M + 2 * KPAD * 4)        // +2432
#define SMEM_R (OFF_VP + 8 * KPAD * 4)       // +9728 = 124800 bytes

__device__ __forceinline__ void fma2(unsigned long long& acc,
                                     unsigned long long a,
                                     unsigned long long b) {
    asm("fma.rn.f32x2 %0, %1, %2, %0;" : "+l"(acc) : "l"(a), "l"(b));
}
__device__ __forceinline__ unsigned long long pk64(unsigned a, unsigned b) {
    unsigned long long r;
    asm("mov.b64 %0, {%1, %2};" : "=l"(r) : "r"(a), "r"(b));
    return r;
}

__global__ void __launch_bounds__(RT, 1) k_recur(const float* __restrict__ Uu) {
    extern __shared__ char sm[];
    uint2* sw = (uint2*)(sm + OFF_SW);           // [JS][RT]
    float* m0dup = (float*)(sm + OFF_M);         // [2*KPAD], {m,m} per k
    float* vpf = (float*)(sm + OFF_VP);          // [8][KPAD]
    int tid = threadIdx.x;
    int kc = tid / 80;
    int dq = tid - kc * 80;
    bool act = (dq < 75);
    int k0 = kc * JT;
    int d0 = dq * 4;

    // ---- prologue: weights into regs (fp32 pairs) and smem (bf16x4) ----
    unsigned long long wr[JR][2];
    if (act) {
#pragma unroll
        for (int j = 0; j < JR; j++) {
            int k = k0 + j;
            float4 w = (k < DD) ? *(const float4*)&Uu[(size_t)k * DD + d0]
                                : make_float4(0.f, 0.f, 0.f, 0.f);
            wr[j][0] = pk64(__float_as_uint(w.x), __float_as_uint(w.y));
            wr[j][1] = pk64(__float_as_uint(w.z), __float_as_uint(w.w));
        }
#pragma unroll
        for (int j = JR; j < JT; j++) {
            int k = k0 + j;
            float4 w = (k < DD) ? *(const float4*)&Uu[(size_t)k * DD + d0]
                                : make_float4(0.f, 0.f, 0.f, 0.f);
            unsigned a = (unsigned)__bfloat16_as_ushort(__float2bfloat16(w.x)) |
                         ((unsigned)__bfloat16_as_ushort(__float2bfloat16(w.y)) << 16);
            unsigned b = (unsigned)__bfloat16_as_ushort(__float2bfloat16(w.z)) |
                         ((unsigned)__bfloat16_as_ushort(__float2bfloat16(w.w)) << 16);
            sw[(size_t)(j - JR) * RT + tid] = make_uint2(a, b);
        }
    }
    for (int i = tid; i < 2 * KPAD; i += RT) m0dup[i] = 0.f;
    __syncthreads();

    const ulonglong2* mp = (const ulonglong2*)&m0dup[2 * k0];  // 16B aligned

    for (int t = 0; t < T_STEPS; t++) {
        float uval = 0.f, pval = 0.f, mold = 0.f;
        if (tid < DD) {
            uval = g_U[(size_t)t * DD + tid];
            pval = g_P0[(size_t)t * DD + tid];
            mold = m0dup[2 * tid];
        }
        if (act) {
            unsigned long long acc0 = 0ULL, acc1 = 0ULL;
#pragma unroll
            for (int j = 0; j < JR; j += 2) {
                ulonglong2 mm = mp[j >> 1];     // {m_k,m_k},{m_k1,m_k1}
                fma2(acc0, wr[j][0], mm.x);
                fma2(acc1, wr[j][1], mm.x);
                fma2(acc0, wr[j + 1][0], mm.y);
                fma2(acc1, wr[j + 1][1], mm.y);
            }
#pragma unroll
            for (int j = JR; j < JT; j += 2) {
                ulonglong2 mm = mp[j >> 1];
                uint2 wa = sw[(size_t)(j - JR) * RT + tid];
                uint2 wb = sw[(size_t)(j - JR + 1) * RT + tid];
                fma2(acc0, pk64(wa.x << 16, wa.x & 0xFFFF0000u), mm.x);
                fma2(acc1, pk64(wa.y << 16, wa.y & 0xFFFF0000u), mm.x);
                fma2(acc0, pk64(wb.x << 16, wb.x & 0xFFFF0000u), mm.y);
                fma2(acc1, pk64(wb.y << 16, wb.y & 0xFFFF0000u), mm.y);
            }
            *(unsigned long long*)&vpf[kc * KPAD + d0] = acc0;      // {v_d0,v_d1}
            *(unsigned long long*)&vpf[kc * KPAD + d0 + 2] = acc1;  // {v_d2,v_d3}
        }
        __syncthreads();
        if (tid < DD) {
            float v = 0.f;
#pragma unroll
            for (int c = 0; c < 8; c++) v += vpf[c * KPAD + tid];
            float z = uval + v;
            float g = 1.f / (1.f + __expf(-z));
            float mn = mold + g * (pval - mold);
            m0dup[2 * tid] = mn;
            m0dup[2 * tid + 1] = mn;
            g_H[(size_t)t * DD + tid] = fmaxf(mn, 0.f);
        }
        __syncthreads();
    }
}

// ---------------- kernel 5: logits = relu(m0) @ Wg^T + bg (f32x2 GEMM) -------
#define BV 64
#define BT 128
#define BK 20

__global__ __launch_bounds__(256) void k_logits(const float* __restrict__ Wg,
                                                const float* __restrict__ bg,
                                                float* __restrict__ out) {
    __shared__ float wgs[BK][BV];
    __shared__ float hs[BK][BT];
    int v0 = blockIdx.x * BV;
    int t0 = blockIdx.y * BT;
    int tid = threadIdx.x;
    int tv = (tid & 15) * 4;   // 4 v per thread
    int tt = (tid >> 4) * 8;   // 8 t per thread (4 packed pairs)

    unsigned long long acc[4][4];
#pragma unroll
    for (int c = 0; c < 4; c++)
#pragma unroll
        for (int j = 0; j < 4; j++) acc[c][j] = 0ULL;

    for (int kb = 0; kb < DD; kb += BK) {
        __syncthreads();
        for (int l = tid; l < BV * 5; l += 256) {
            int a = l / 5, q = l - (l / 5) * 5;
            float4 w = *(const float4*)&Wg[(size_t)(v0 + a) * DD + kb + q * 4];
            wgs[q * 4 + 0][a] = w.x; wgs[q * 4 + 1][a] = w.y;
            wgs[q * 4 + 2][a] = w.z; wgs[q * 4 + 3][a] = w.w;
        }
        for (int l = tid; l < BT * 5; l += 256) {
            int i = l / 5, q = l - (l / 5) * 5;
            float4 h = *(const float4*)&g_H[(size_t)(t0 + i) * DD + kb + q * 4];
            hs[q * 4 + 0][i] = h.x; hs[q * 4 + 1][i] = h.y;
            hs[q * 4 + 2][i] = h.z; hs[q * 4 + 3][i] = h.w;
        }
        __syncthreads();
#pragma unroll
        for (int k = 0; k < BK; k++) {
            unsigned long long hp[4];
#pragma unroll
            for (int j = 0; j < 4; j++)
                hp[j] = *(const unsigned long long*)&hs[k][tt + 2 * j];
#pragma unroll
            for (int c = 0; c < 4; c++) {
                float w = wgs[k][tv + c];
                unsigned long long wp;
                asm("mov.b64 %0, {%1, %1};" : "=l"(wp) : "f"(w));
#pragma unroll
                for (int j = 0; j < 4; j++)
                    asm("fma.rn.f32x2 %0, %1, %2, %0;"
                        : "+l"(acc[c][j]) : "l"(hp[j]), "l"(wp));
            }
        }
    }
#pragma unroll
    for (int c = 0; c < 4; c++) {
        int v = v0 + tv + c;
        float b = bg[v];
#pragma unroll
        for (int j = 0; j < 4; j++) {
            float lo = __uint_as_float((unsigned)(acc[c][j] & 0xFFFFFFFFULL));
            float hi = __uint_as_float((unsigned)(acc[c][j] >> 32));
            int t = t0 + tt + 2 * j;
            out[(size_t)t * VGN + v] = lo + b;
            out[(size_t)(t + 1) * VGN + v] = hi + b;
        }
    }
}

// ---------------- kernel 6: in-place log_softmax per row ----------------
__global__ __launch_bounds__(512) void k_logsoftmax(float* __restrict__ out) {
    int t = blockIdx.x;
    float* row = out + (size_t)t * VGN;
    __shared__ float red[32];
    int tid = threadIdx.x;

    float m = -1e30f;
    for (int v = tid; v < VGN; v += blockDim.x) m = fmaxf(m, row[v]);
#pragma unroll
    for (int o = 16; o; o >>= 1) m = fmaxf(m, __shfl_xor_sync(~0u, m, o));
    if ((tid & 31) == 0) red[tid >> 5] = m;
    __syncthreads();
    if (tid < 32) {
        float x = (tid < (int)(blockDim.x >> 5)) ? red[tid] : -1e30f;
#pragma unroll
        for (int o = 16; o; o >>= 1) x = fmaxf(x, __shfl_xor_sync(~0u, x, o));
        if (tid == 0) red[0] = x;
    }
    __syncthreads();
    m = red[0];
    __syncthreads();

    float s = 0.f;
    for (int v = tid; v < VGN; v += blockDim.x) s += __expf(row[v] - m);
#pragma unroll
    for (int o = 16; o; o >>= 1) s += __shfl_xor_sync(~0u, s, o);
    if ((tid & 31) == 0) red[tid >> 5] = s;
    __syncthreads();
    if (tid < 32) {
        float x = (tid < (int)(blockDim.x >> 5)) ? red[tid] : 0.f;
#pragma unroll
        for (int o = 16; o; o >>= 1) x += __shfl_xor_sync(~0u, x, o);
        if (tid == 0) red[0] = x;
    }
    __syncthreads();
    float lse = m + logf(red[0]);
    for (int v = tid; v < VGN; v += blockDim.x) row[v] -= lse;
}

// ---------------- tail zero (second ref output = zeros) ----------------
__global__ void k_zero(float* out, size_t start, size_t n) {
    size_t i = (size_t)blockIdx.x * blockDim.x + threadIdx.x;
    if (i < n) out[start + i] = 0.f;
}

extern "C" void kernel_launch(void* const* d_in, const int* in_sizes, int n_in,
                              void* d_out, int out_size) {
    const int*   xidx  = (const int*)d_in[0];
    const int*   esrc  = (const int*)d_in[1];
    const int*   edst  = (const int*)d_in[2];
    const float* X     = (const float*)d_in[3];
    const float* convW = (const float*)d_in[4];
    const float* W0    = (const float*)d_in[5];
    const float* Wu    = (const float*)d_in[6];
    const float* Uu    = (const float*)d_in[7];
    const float* Wg    = (const float*)d_in[8];
    const float* bg    = (const float*)d_in[9];
    float* out = (float*)d_out;

    cudaFuncSetAttribute(k_recur, cudaFuncAttributeMaxDynamicSharedMemorySize, SMEM_R);

    k_gather<<<T_STEPS, 256>>>(xidx, X);
    k_ugemm<<<dim3(T_STEPS / UT, UKS), 320>>>(Wu);
    k_coefY<<<T_STEPS, 128>>>(esrc, edst);
    k_pgemm<<<dim3(T_STEPS / PT, 4), 320>>>(convW, W0);
    k_reduce2<<<(TD + 255) / 256, 256>>>();
    k_recur<<<1, RT, SMEM_R>>>(Uu);
    k_logits<<<dim3(VGN / BV, T_STEPS / BT), 256>>>(Wg, bg, out);
    k_logsoftmax<<<T_STEPS, 512>>>(out);

    size_t used = (size_t)T_STEPS * VGN;
    if ((size_t)out_size > used) {
        size_t n = (size_t)out_size - used;
        k_zero<<<(unsigned)((n + 255) / 256), 256>>>(out, used, n);
    }
}

// round 5
// speedup vs baseline: 1.9050x; 1.3080x over previous
#include <cuda_runtime.h>
#include <cuda_bf16.h>
#include <cstdint>

#define T_STEPS 512
#define NN 32
#define DD 300
#define RR 3
#define EE 64
#define VGN 40000
#define KFLAT 9600   // NN*DD
#define TD (T_STEPS * DD)

#define KP 320       // padded K for tensor-core logits
#define VP 40064     // padded V rows (313 x 128)

// ---------------- scratch (device globals; no allocs allowed) ----------------
__device__ float g_Xg[(size_t)T_STEPS * KFLAT];        // gathered x  [512][9600]
__device__ float g_Upart[(size_t)16 * TD];             // U split-k partials
__device__ float g_Ppart[(size_t)4 * TD];              // P0 split-s partials
__device__ float g_Y[(size_t)T_STEPS * 4 * DD];        // aggregated rows per (t,s)
__device__ float g_U[(size_t)TD];                      // u_t = x_flat @ Wu
__device__ float g_P0[(size_t)TD];                     // proposed row 0 per t
__device__ __nv_bfloat16 g_Hb[(size_t)T_STEPS * KP];   // relu(new_mem[0]) bf16 padded
__device__ __nv_bfloat16 g_Wgb[(size_t)VP * KP];       // Wg bf16 padded

// ---------------- helpers ----------------
__device__ __forceinline__ void fma2(unsigned long long& acc,
                                     unsigned long long a,
                                     unsigned long long b) {
    asm("fma.rn.f32x2 %0, %1, %2, %0;" : "+l"(acc) : "l"(a), "l"(b));
}
__device__ __forceinline__ unsigned long long pk64(unsigned a, unsigned b) {
    unsigned long long r;
    asm("mov.b64 %0, {%1, %2};" : "=l"(r) : "r"(a), "r"(b));
    return r;
}
__device__ __forceinline__ uint32_t smem_u32(const void* p) {
    uint32_t a;
    asm("{ .reg .u64 t; cvta.to.shared.u64 t, %1; cvt.u32.u64 %0, t; }" : "=r"(a) : "l"(p));
    return a;
}

// ---------------- kernel 1: gather x rows ----------------
__global__ void k_gather(const int* __restrict__ xidx, const float* __restrict__ X) {
    int t = blockIdx.x;
    __shared__ int ids[NN];
    if (threadIdx.x < NN) ids[threadIdx.x] = xidx[t * NN + threadIdx.x];
    __syncthreads();
    for (int i = threadIdx.x; i < KFLAT; i += blockDim.x) {
        int n = i / DD;
        int k = i - n * DD;
        g_Xg[(size_t)t * KFLAT + i] = X[(size_t)ids[n] * DD + k];
    }
}

// ---------------- kernel 1b: Wg -> bf16 padded [VP][KP] ----------------
__global__ void k_cvtW(const float* __restrict__ Wg) {
    size_t i = ((size_t)blockIdx.x * blockDim.x + threadIdx.x) * 2;  // 2 bf16 per thread
    if (i >= (size_t)VP * KP) return;
    int v = (int)(i / KP), k = (int)(i - (size_t)v * KP);
    float a = (v < VGN && k < DD) ? Wg[(size_t)v * DD + k] : 0.f;
    float b = (v < VGN && k + 1 < DD) ? Wg[(size_t)v * DD + k + 1] : 0.f;
    unsigned pa = (unsigned)__bfloat16_as_ushort(__float2bfloat16(a)) |
                  ((unsigned)__bfloat16_as_ushort(__float2bfloat16(b)) << 16);
    *(unsigned*)&g_Wgb[i] = pa;
}

// ---------------- kernel 2: U = Xg @ Wu, split-k, f32x2 over t-pairs ----------
#define UT 16    // t per CTA (8 packed pairs)
#define UKS 16   // k splits
#define UK 600   // k per CTA (9600/16)
#define UC 40    // k chunk in smem

__global__ __launch_bounds__(320) void k_ugemm(const float* __restrict__ Wu) {
    int t0 = blockIdx.x * UT;
    int ks = blockIdx.y;
    int kbase = ks * UK;
    int d = threadIdx.x;
    __shared__ unsigned long long xs2[UC][8];   // [k][t-pair] = {x_t0, x_t1}
    unsigned long long acc[8];
#pragma unroll
    for (int i = 0; i < 8; i++) acc[i] = 0ULL;

    for (int c = 0; c < UK; c += UC) {
        __syncthreads();
        for (int l = threadIdx.x; l < 8 * UC; l += 320) {
            int i2 = l / UC, j = l - (l / UC) * UC;
            int kk = kbase + c + j;
            float a = g_Xg[(size_t)(t0 + 2 * i2) * KFLAT + kk];
            float b = g_Xg[(size_t)(t0 + 2 * i2 + 1) * KFLAT + kk];
            xs2[j][i2] = pk64(__float_as_uint(a), __float_as_uint(b));
        }
        __syncthreads();
        if (d < DD) {
#pragma unroll 5
            for (int j = 0; j < UC; j++) {
                float w = Wu[(size_t)(kbase + c + j) * DD + d];
                unsigned long long wp;
                asm("mov.b64 %0, {%1, %1};" : "=l"(wp) : "f"(w));
                const ulonglong2* xp = (const ulonglong2*)&xs2[j][0];
                ulonglong2 x01 = xp[0], x23 = xp[1], x45 = xp[2], x67 = xp[3];
                fma2(acc[0], x01.x, wp); fma2(acc[1], x01.y, wp);
                fma2(acc[2], x23.x, wp); fma2(acc[3], x23.y, wp);
                fma2(acc[4], x45.x, wp); fma2(acc[5], x45.y, wp);
                fma2(acc[6], x67.x, wp); fma2(acc[7], x67.y, wp);
            }
        }
    }
    if (d < DD) {
#pragma unroll
        for (int i = 0; i < 8; i++) {
            unsigned lo, hi;
            asm("mov.b64 {%0, %1}, %2;" : "=r"(lo), "=r"(hi) : "l"(acc[i]));
            g_Upart[((size_t)ks * T_STEPS + (t0 + 2 * i)) * DD + d] = __uint_as_float(lo);
            g_Upart[((size_t)ks * T_STEPS + (t0 + 2 * i + 1)) * DD + d] = __uint_as_float(hi);
        }
    }
}

// ---------------- kernel 3a: per-t coefficients + aggregated rows Y ----------
__global__ __launch_bounds__(128) void k_coefY(const int* __restrict__ esrc,
                                               const int* __restrict__ edst) {
    int t = blockIdx.x;
    int tid = threadIdx.x;
    __shared__ int cnt[RR][NN];
    __shared__ float dinv[RR][NN];
    __shared__ float cval[RR][NN + 1];
    __shared__ int cidx[RR][NN + 1];
    __shared__ int cn[RR];

    if (tid < RR * NN) cnt[tid / NN][tid % NN] = 0;
    __syncthreads();

    const int* es = esrc + (size_t)t * RR * EE;
    const int* ed = edst + (size_t)t * RR * EE;
    for (int j = tid; j < RR * EE; j += 128)
        atomicAdd(&cnt[j / EE][ed[j]], 1);   // integer atomics: deterministic
    __syncthreads();

    if (tid < RR * NN) {
        int r = tid / NN, n = tid % NN;
        dinv[r][n] = rsqrtf((float)(cnt[r][n] + 1));  // deg includes self-loop
    }
    __syncthreads();

    if (tid < RR) {
        int r = tid;
        float c[NN];
#pragma unroll
        for (int n = 0; n < NN; n++) c[n] = 0.f;
        for (int e = 0; e < EE; e++) {
            if (ed[r * EE + e] == 0) {
                int s = es[r * EE + e];
                c[s] += dinv[r][s];
            }
        }
        float d0 = dinv[r][0];
        c[0] += d0;               // self loop: (c0 + d0)*d0 == c0*d0 + d0^2
        int m = 0;
        for (int n = 0; n < NN; n++) {
            if (c[n] != 0.f) { cidx[r][m] = n; cval[r][m] = c[n] * d0; m++; }
        }
        cn[r] = m;
    }
    __syncthreads();

    const float* xg = g_Xg + (size_t)t * KFLAT;
    float* Yt = g_Y + (size_t)t * 4 * DD;
    for (int k = tid; k < DD; k += 128) {
        Yt[k] = xg[k];   // s=0: x0 (for W0 term)
#pragma unroll
        for (int r = 0; r < RR; r++) {
            float a = 0.f;
            int m = cn[r];
            for (int q = 0; q < m; q++)
                a += cval[r][q] * xg[cidx[r][q] * DD + k];
            Yt[(r + 1) * DD + k] = a;
        }
    }
}

// ---------------- kernel 3b: P0 partials = Y[:,s,:] @ Ws ----------------
#define PT 8

__global__ __launch_bounds__(320) void k_pgemm(const float* __restrict__ convW,
                                               const float* __restrict__ W0) {
    int t0 = blockIdx.x * PT;
    int s = blockIdx.y;
    const float* W = (s == 0) ? W0 : (convW + (size_t)(s - 1) * DD * DD);
    int d = threadIdx.x;
    __shared__ float ys[PT][60];
    float acc[PT];
#pragma unroll
    for (int i = 0; i < PT; i++) acc[i] = 0.f;

    for (int c = 0; c < DD; c += 60) {
        __syncthreads();
        for (int l = threadIdx.x; l < PT * 60; l += 320) {
            int i = l / 60, j = l - (l / 60) * 60;
            ys[i][j] = g_Y[((size_t)(t0 + i) * 4 + s) * DD + c + j];
        }
        __syncthreads();
        if (d < DD) {
#pragma unroll 10
            for (int j = 0; j < 60; j++) {
                float w = W[(size_t)(c + j) * DD + d];
#pragma unroll
                for (int i = 0; i < PT; i++) acc[i] += ys[i][j] * w;
            }
        }
    }
    if (d < DD) {
#pragma unroll
        for (int i = 0; i < PT; i++)
            g_Ppart[((size_t)s * T_STEPS + t0 + i) * DD + d] = acc[i];
    }
}

// ---------------- kernel 3c: reduce U (16) and P0 (4) partials ----------------
__global__ void k_reduce2() {
    int i = blockIdx.x * blockDim.x + threadIdx.x;
    if (i < TD) {
        float s = 0.f;
#pragma unroll
        for (int p = 0; p < UKS; p++) s += g_Upart[(size_t)p * TD + i];
        g_U[i] = s;
        float q = 0.f;
#pragma unroll
        for (int p = 0; p < 4; p++) q += g_Ppart[(size_t)p * TD + i];
        g_P0[i] = q;
    }
}

// ---------------- kernel 4: sequential recurrence (single CTA) ----------------
#define RT 640
#define JT 38
#define JR 16
#define JS (JT - JR)          // 22
#define KPAD 304
#define OFF_SW 0
#define OFF_M  (JS * RT * 8)                 // 112640 (16B aligned)
#define OFF_VP (OFF_M + 2 * KPAD * 4)        // +2432
#define SMEM_R (OFF_VP + 8 * KPAD * 4)       // +9728 = 124800 bytes

__global__ void __launch_bounds__(RT, 1) k_recur(const float* __restrict__ Uu) {
    extern __shared__ char sm[];
    uint2* sw = (uint2*)(sm + OFF_SW);           // [JS][RT]
    float* m0dup = (float*)(sm + OFF_M);         // [2*KPAD], {m,m} per k
    float* vpf = (float*)(sm + OFF_VP);          // [8][KPAD]
    int tid = threadIdx.x;
    int kc = tid / 80;
    int dq = tid - kc * 80;
    bool act = (dq < 75);
    int k0 = kc * JT;
    int d0 = dq * 4;

    // ---- prologue: weights into regs (fp32 pairs) and smem (bf16x4) ----
    unsigned long long wr[JR][2];
    if (act) {
#pragma unroll
        for (int j = 0; j < JR; j++) {
            int k = k0 + j;
            float4 w = (k < DD) ? *(const float4*)&Uu[(size_t)k * DD + d0]
                                : make_float4(0.f, 0.f, 0.f, 0.f);
            wr[j][0] = pk64(__float_as_uint(w.x), __float_as_uint(w.y));
            wr[j][1] = pk64(__float_as_uint(w.z), __float_as_uint(w.w));
        }
#pragma unroll
        for (int j = JR; j < JT; j++) {
            int k = k0 + j;
            float4 w = (k < DD) ? *(const float4*)&Uu[(size_t)k * DD + d0]
                                : make_float4(0.f, 0.f, 0.f, 0.f);
            unsigned a = (unsigned)__bfloat16_as_ushort(__float2bfloat16(w.x)) |
                         ((unsigned)__bfloat16_as_ushort(__float2bfloat16(w.y)) << 16);
            unsigned b = (unsigned)__bfloat16_as_ushort(__float2bfloat16(w.z)) |
                         ((unsigned)__bfloat16_as_ushort(__float2bfloat16(w.w)) << 16);
            sw[(size_t)(j - JR) * RT + tid] = make_uint2(a, b);
        }
    }
    for (int i = tid; i < 2 * KPAD; i += RT) m0dup[i] = 0.f;
    __syncthreads();

    const ulonglong2* mp = (const ulonglong2*)&m0dup[2 * k0];  // 16B aligned

    for (int t = 0; t < T_STEPS; t++) {
        float uval = 0.f, pval = 0.f, mold = 0.f;
        if (tid < DD) {
            uval = g_U[(size_t)t * DD + tid];
            pval = g_P0[(size_t)t * DD + tid];
            mold = m0dup[2 * tid];
        }
        if (act) {
            unsigned long long acc0 = 0ULL, acc1 = 0ULL;
#pragma unroll
            for (int j = 0; j < JR; j += 2) {
                ulonglong2 mm = mp[j >> 1];     // {m_k,m_k},{m_k1,m_k1}
                fma2(acc0, wr[j][0], mm.x);
                fma2(acc1, wr[j][1], mm.x);
                fma2(acc0, wr[j + 1][0], mm.y);
                fma2(acc1, wr[j + 1][1], mm.y);
            }
#pragma unroll
            for (int j = JR; j < JT; j += 2) {
                ulonglong2 mm = mp[j >> 1];
                uint2 wa = sw[(size_t)(j - JR) * RT + tid];
                uint2 wb = sw[(size_t)(j - JR + 1) * RT + tid];
                fma2(acc0, pk64(wa.x << 16, wa.x & 0xFFFF0000u), mm.x);
                fma2(acc1, pk64(wa.y << 16, wa.y & 0xFFFF0000u), mm.x);
                fma2(acc0, pk64(wb.x << 16, wb.x & 0xFFFF0000u), mm.y);
                fma2(acc1, pk64(wb.y << 16, wb.y & 0xFFFF0000u), mm.y);
            }
            *(unsigned long long*)&vpf[kc * KPAD + d0] = acc0;      // {v_d0,v_d1}
            *(unsigned long long*)&vpf[kc * KPAD + d0 + 2] = acc1;  // {v_d2,v_d3}
        }
        __syncthreads();
        if (tid < DD) {
            float v = 0.f;
#pragma unroll
            for (int c = 0; c < 8; c++) v += vpf[c * KPAD + tid];
            float z = uval + v;
            float g = 1.f / (1.f + __expf(-z));
            float mn = mold + g * (pval - mold);
            m0dup[2 * tid] = mn;
            m0dup[2 * tid + 1] = mn;
            g_Hb[(size_t)t * KP + tid] = __float2bfloat16(fmaxf(mn, 0.f));
        } else if (tid < KP) {
            g_Hb[(size_t)t * KP + tid] = __float2bfloat16(0.f);
        }
        __syncthreads();
    }
}

// ---------------- kernel 5: logits via mma.sync bf16 (baseline PTX HMMA) -----
// C[128 t][128 v] per CTA. 8 warps: 2x4 (m x n), each 64x32.
// K chunks of 32 in smem, pitch 40 bf16 (conflict-free ldmatrix).
#define LPITCH 40

__device__ __forceinline__ void ldm_x4(uint32_t* f, uint32_t addr) {
    asm volatile("ldmatrix.sync.aligned.m8n8.x4.shared.b16 {%0,%1,%2,%3}, [%4];"
                 : "=r"(f[0]), "=r"(f[1]), "=r"(f[2]), "=r"(f[3]) : "r"(addr));
}
__device__ __forceinline__ void mma_bf16(float* c, const uint32_t* a,
                                         uint32_t b0, uint32_t b1) {
    asm volatile(
        "mma.sync.aligned.m16n8k16.row.col.f32.bf16.bf16.f32 "
        "{%0,%1,%2,%3}, {%4,%5,%6,%7}, {%8,%9}, {%0,%1,%2,%3};"
        : "+f"(c[0]), "+f"(c[1]), "+f"(c[2]), "+f"(c[3])
        : "r"(a[0]), "r"(a[1]), "r"(a[2]), "r"(a[3]), "r"(b0), "r"(b1));
}

__global__ __launch_bounds__(256) void k_logits_mma(const float* __restrict__ bg,
                                                    float* __restrict__ out) {
    __shared__ __align__(16) __nv_bfloat16 As[128 * LPITCH];
    __shared__ __align__(16) __nv_bfloat16 Bs[128 * LPITCH];
    int tid = threadIdx.x;
    int wid = tid >> 5, lane = tid & 31;
    int wm = wid & 1, wn = wid >> 1;
    int v0 = blockIdx.x * 128;
    int t0 = blockIdx.y * 128;

    float acc[4][4][4];
#pragma unroll
    for (int mt = 0; mt < 4; mt++)
#pragma unroll
        for (int nt = 0; nt < 4; nt++)
#pragma unroll
            for (int r = 0; r < 4; r++) acc[mt][nt][r] = 0.f;

    uint32_t sA = smem_u32(As), sB = smem_u32(Bs);
    int lrow = lane & 15;
    int lcol = (lane >> 4) << 3;

    for (int kb = 0; kb < KP; kb += 32) {
        __syncthreads();
#pragma unroll
        for (int h = 0; h < 2; h++) {
            int c = tid + h * 256;
            int r = c >> 2, q = c & 3;
            *(uint4*)(As + r * LPITCH + q * 8) =
                *(const uint4*)&g_Hb[(size_t)(t0 + r) * KP + kb + q * 8];
            *(uint4*)(Bs + r * LPITCH + q * 8) =
                *(const uint4*)&g_Wgb[(size_t)(v0 + r) * KP + kb + q * 8];
        }
        __syncthreads();
#pragma unroll
        for (int ks = 0; ks < 32; ks += 16) {
            uint32_t af[4][4], bf[2][4];
#pragma unroll
            for (int mt = 0; mt < 4; mt++)
                ldm_x4(af[mt],
                       sA + (uint32_t)(((wm * 64 + mt * 16 + lrow) * LPITCH + ks + lcol) * 2));
#pragma unroll
            for (int np = 0; np < 2; np++)
                ldm_x4(bf[np],
                       sB + (uint32_t)(((wn * 32 + np * 16 + lrow) * LPITCH + ks + lcol) * 2));
#pragma unroll
            for (int mt = 0; mt < 4; mt++) {
#pragma unroll
                for (int nt = 0; nt < 4; nt++) {
                    int np = nt >> 1, sub = nt & 1;
                    mma_bf16(acc[mt][nt], af[mt], bf[np][sub], bf[np][sub + 2]);
                }
            }
        }
    }

    // epilogue: bias + guarded stores
    int grp = lane >> 2, qc = (lane & 3) * 2;
#pragma unroll
    for (int nt = 0; nt < 4; nt++) {
        int v = v0 + wn * 32 + nt * 8 + qc;
        if (v >= VGN) continue;
        float b0 = bg[v], b1 = bg[v + 1];
#pragma unroll
        for (int mt = 0; mt < 4; mt++) {
            int t = t0 + wm * 64 + mt * 16 + grp;
            float2 o0 = make_float2(acc[mt][nt][0] + b0, acc[mt][nt][1] + b1);
            float2 o1 = make_float2(acc[mt][nt][2] + b0, acc[mt][nt][3] + b1);
            *(float2*)&out[(size_t)t * VGN + v] = o0;
            *(float2*)&out[(size_t)(t + 8) * VGN + v] = o1;
        }
    }
}

// ---------------- kernel 6: in-place log_softmax per row ----------------
__global__ __launch_bounds__(512) void k_logsoftmax(float* __restrict__ out) {
    int t = blockIdx.x;
    float* row = out + (size_t)t * VGN;
    __shared__ float red[32];
    int tid = threadIdx.x;

    float m = -1e30f;
    for (int v = tid; v < VGN; v += blockDim.x) m = fmaxf(m, row[v]);
#pragma unroll
    for (int o = 16; o; o >>= 1) m = fmaxf(m, __shfl_xor_sync(~0u, m, o));
    if ((tid & 31) == 0) red[tid >> 5] = m;
    __syncthreads();
    if (tid < 32) {
        float x = (tid < (int)(blockDim.x >> 5)) ? red[tid] : -1e30f;
#pragma unroll
        for (int o = 16; o; o >>= 1) x = fmaxf(x, __shfl_xor_sync(~0u, x, o));
        if (tid == 0) red[0] = x;
    }
    __syncthreads();
    m = red[0];
    __syncthreads();

    float s = 0.f;
    for (int v = tid; v < VGN; v += blockDim.x) s += __expf(row[v] - m);
#pragma unroll
    for (int o = 16; o; o >>= 1) s += __shfl_xor_sync(~0u, s, o);
    if ((tid & 31) == 0) red[tid >> 5] = s;
    __syncthreads();
    if (tid < 32) {
        float x = (tid < (int)(blockDim.x >> 5)) ? red[tid] : 0.f;
#pragma unroll
        for (int o = 16; o; o >>= 1) x += __shfl_xor_sync(~0u, x, o);
        if (tid == 0) red[0] = x;
    }
    __syncthreads();
    float lse = m + logf(red[0]);
    for (int v = tid; v < VGN; v += blockDim.x) row[v] -= lse;
}

// ---------------- tail zero (second ref output = zeros) ----------------
__global__ void k_zero(float* out, size_t start, size_t n) {
    size_t i = (size_t)blockIdx.x * blockDim.x + threadIdx.x;
    if (i < n) out[start + i] = 0.f;
}

extern "C" void kernel_launch(void* const* d_in, const int* in_sizes, int n_in,
                              void* d_out, int out_size) {
    const int*   xidx  = (const int*)d_in[0];
    const int*   esrc  = (const int*)d_in[1];
    const int*   edst  = (const int*)d_in[2];
    const float* X     = (const float*)d_in[3];
    const float* convW = (const float*)d_in[4];
    const float* W0    = (const float*)d_in[5];
    const float* Wu    = (const float*)d_in[6];
    const float* Uu    = (const float*)d_in[7];
    const float* Wg    = (const float*)d_in[8];
    const float* bg    = (const float*)d_in[9];
    float* out = (float*)d_out;

    cudaFuncSetAttribute(k_recur, cudaFuncAttributeMaxDynamicSharedMemorySize, SMEM_R);

    k_gather<<<T_STEPS, 256>>>(xidx, X);
    {
        size_t nw = ((size_t)VP * KP) / 2;
        k_cvtW<<<(unsigned)((nw + 255) / 256), 256>>>(Wg);
    }
    k_ugemm<<<dim3(T_STEPS / UT, UKS), 320>>>(Wu);
    k_coefY<<<T_STEPS, 128>>>(esrc, edst);
    k_pgemm<<<dim3(T_STEPS / PT, 4), 320>>>(convW, W0);
    k_reduce2<<<(TD + 255) / 256, 256>>>();
    k_recur<<<1, RT, SMEM_R>>>(Uu);
    k_logits_mma<<<dim3(VP / 128, T_STEPS / 128), 256>>>(bg, out);
    k_logsoftmax<<<T_STEPS, 512>>>(out);

    size_t used = (size_t)T_STEPS * VGN;
    if ((size_t)out_size > used) {
        size_t n = (size_t)out_size - used;
        k_zero<<<(unsigned)((n + 255) / 256), 256>>>(out, used, n);
    }
}

// round 6
// speedup vs baseline: 2.2436x; 1.1777x over previous
#include <cuda_runtime.h>
#include <cuda_bf16.h>
#include <cstdint>

#define T_STEPS 512
#define NN 32
#define DD 300
#define RR 3
#define EE 64
#define VGN 40000
#define KFLAT 9600   // NN*DD
#define TD (T_STEPS * DD)

#define KP 320       // padded K for tensor-core logits (and recur k pad)
#define VP 40064     // padded V rows (313 x 128)

// ---------------- scratch (device globals; no allocs allowed) ----------------
__device__ float g_Xg[(size_t)T_STEPS * KFLAT];        // gathered x  [512][9600]
__device__ float g_Upart[(size_t)16 * TD];             // U split-k partials
__device__ float g_Ppart[(size_t)4 * TD];              // P0 split-s partials
__device__ float g_Y[(size_t)T_STEPS * 4 * DD];        // aggregated rows per (t,s)
__device__ float g_U[(size_t)TD];                      // u_t = x_flat @ Wu
__device__ float g_P0[(size_t)TD];                     // proposed row 0 per t
__device__ __nv_bfloat16 g_Hb[(size_t)T_STEPS * KP];   // relu(new_mem[0]) bf16 padded
__device__ __nv_bfloat16 g_Wgb[(size_t)VP * KP];       // Wg bf16 padded

// ---------------- helpers ----------------
__device__ __forceinline__ void fma2(unsigned long long& acc,
                                     unsigned long long a,
                                     unsigned long long b) {
    asm("fma.rn.f32x2 %0, %1, %2, %0;" : "+l"(acc) : "l"(a), "l"(b));
}
__device__ __forceinline__ unsigned long long pk64(unsigned a, unsigned b) {
    unsigned long long r;
    asm("mov.b64 %0, {%1, %2};" : "=l"(r) : "r"(a), "r"(b));
    return r;
}
__device__ __forceinline__ uint32_t smem_u32(const void* p) {
    uint32_t a;
    asm("{ .reg .u64 t; cvta.to.shared.u64 t, %1; cvt.u32.u64 %0, t; }" : "=r"(a) : "l"(p));
    return a;
}

// ---------------- kernel 1: gather x rows ----------------
__global__ void k_gather(const int* __restrict__ xidx, const float* __restrict__ X) {
    int t = blockIdx.x;
    __shared__ int ids[NN];
    if (threadIdx.x < NN) ids[threadIdx.x] = xidx[t * NN + threadIdx.x];
    __syncthreads();
    for (int i = threadIdx.x; i < KFLAT; i += blockDim.x) {
        int n = i / DD;
        int k = i - n * DD;
        g_Xg[(size_t)t * KFLAT + i] = X[(size_t)ids[n] * DD + k];
    }
}

// ---------------- kernel 1b: Wg -> bf16 padded [VP][KP] ----------------
__global__ void k_cvtW(const float* __restrict__ Wg) {
    size_t i = ((size_t)blockIdx.x * blockDim.x + threadIdx.x) * 2;  // 2 bf16 per thread
    if (i >= (size_t)VP * KP) return;
    int v = (int)(i / KP), k = (int)(i - (size_t)v * KP);
    float a = (v < VGN && k < DD) ? Wg[(size_t)v * DD + k] : 0.f;
    float b = (v < VGN && k + 1 < DD) ? Wg[(size_t)v * DD + k + 1] : 0.f;
    unsigned pa = (unsigned)__bfloat16_as_ushort(__float2bfloat16(a)) |
                  ((unsigned)__bfloat16_as_ushort(__float2bfloat16(b)) << 16);
    *(unsigned*)&g_Wgb[i] = pa;
}

// ---------------- kernel 1c: zero g_Hb pad columns [300,320) once ------------
__global__ void k_padH() {
    int i = blockIdx.x * blockDim.x + threadIdx.x;
    if (i < T_STEPS * 20) {
        int t = i / 20, k = 300 + (i - (i / 20) * 20);
        g_Hb[(size_t)t * KP + k] = __float2bfloat16(0.f);
    }
}

// ---------------- kernel 2: U = Xg @ Wu, split-k, f32x2 over t-pairs ----------
#define UT 16    // t per CTA (8 packed pairs)
#define UKS 16   // k splits
#define UK 600   // k per CTA (9600/16)
#define UC 40    // k chunk in smem

__global__ __launch_bounds__(320) void k_ugemm(const float* __restrict__ Wu) {
    int t0 = blockIdx.x * UT;
    int ks = blockIdx.y;
    int kbase = ks * UK;
    int d = threadIdx.x;
    __shared__ unsigned long long xs2[UC][8];   // [k][t-pair] = {x_t0, x_t1}
    unsigned long long acc[8];
#pragma unroll
    for (int i = 0; i < 8; i++) acc[i] = 0ULL;

    for (int c = 0; c < UK; c += UC) {
        __syncthreads();
        for (int l = threadIdx.x; l < 8 * UC; l += 320) {
            int i2 = l / UC, j = l - (l / UC) * UC;
            int kk = kbase + c + j;
            float a = g_Xg[(size_t)(t0 + 2 * i2) * KFLAT + kk];
            float b = g_Xg[(size_t)(t0 + 2 * i2 + 1) * KFLAT + kk];
            xs2[j][i2] = pk64(__float_as_uint(a), __float_as_uint(b));
        }
        __syncthreads();
        if (d < DD) {
#pragma unroll 5
            for (int j = 0; j < UC; j++) {
                float w = Wu[(size_t)(kbase + c + j) * DD + d];
                unsigned long long wp;
                asm("mov.b64 %0, {%1, %1};" : "=l"(wp) : "f"(w));
                const ulonglong2* xp = (const ulonglong2*)&xs2[j][0];
                ulonglong2 x01 = xp[0], x23 = xp[1], x45 = xp[2], x67 = xp[3];
                fma2(acc[0], x01.x, wp); fma2(acc[1], x01.y, wp);
                fma2(acc[2], x23.x, wp); fma2(acc[3], x23.y, wp);
                fma2(acc[4], x45.x, wp); fma2(acc[5], x45.y, wp);
                fma2(acc[6], x67.x, wp); fma2(acc[7], x67.y, wp);
            }
        }
    }
    if (d < DD) {
#pragma unroll
        for (int i = 0; i < 8; i++) {
            unsigned lo, hi;
            asm("mov.b64 {%0, %1}, %2;" : "=r"(lo), "=r"(hi) : "l"(acc[i]));
            g_Upart[((size_t)ks * T_STEPS + (t0 + 2 * i)) * DD + d] = __uint_as_float(lo);
            g_Upart[((size_t)ks * T_STEPS + (t0 + 2 * i + 1)) * DD + d] = __uint_as_float(hi);
        }
    }
}

// ---------------- kernel 3a: per-t coefficients + aggregated rows Y ----------
__global__ __launch_bounds__(128) void k_coefY(const int* __restrict__ esrc,
                                               const int* __restrict__ edst) {
    int t = blockIdx.x;
    int tid = threadIdx.x;
    __shared__ int cnt[RR][NN];
    __shared__ float dinv[RR][NN];
    __shared__ float cval[RR][NN + 1];
    __shared__ int cidx[RR][NN + 1];
    __shared__ int cn[RR];

    if (tid < RR * NN) cnt[tid / NN][tid % NN] = 0;
    __syncthreads();

    const int* es = esrc + (size_t)t * RR * EE;
    const int* ed = edst + (size_t)t * RR * EE;
    for (int j = tid; j < RR * EE; j += 128)
        atomicAdd(&cnt[j / EE][ed[j]], 1);   // integer atomics: deterministic
    __syncthreads();

    if (tid < RR * NN) {
        int r = tid / NN, n = tid % NN;
        dinv[r][n] = rsqrtf((float)(cnt[r][n] + 1));  // deg includes self-loop
    }
    __syncthreads();

    if (tid < RR) {
        int r = tid;
        float c[NN];
#pragma unroll
        for (int n = 0; n < NN; n++) c[n] = 0.f;
        for (int e = 0; e < EE; e++) {
            if (ed[r * EE + e] == 0) {
                int s = es[r * EE + e];
                c[s] += dinv[r][s];
            }
        }
        float d0 = dinv[r][0];
        c[0] += d0;               // self loop: (c0 + d0)*d0 == c0*d0 + d0^2
        int m = 0;
        for (int n = 0; n < NN; n++) {
            if (c[n] != 0.f) { cidx[r][m] = n; cval[r][m] = c[n] * d0; m++; }
        }
        cn[r] = m;
    }
    __syncthreads();

    const float* xg = g_Xg + (size_t)t * KFLAT;
    float* Yt = g_Y + (size_t)t * 4 * DD;
    for (int k = tid; k < DD; k += 128) {
        Yt[k] = xg[k];   // s=0: x0 (for W0 term)
#pragma unroll
        for (int r = 0; r < RR; r++) {
            float a = 0.f;
            int m = cn[r];
            for (int q = 0; q < m; q++)
                a += cval[r][q] * xg[cidx[r][q] * DD + k];
            Yt[(r + 1) * DD + k] = a;
        }
    }
}

// ---------------- kernel 3b: P0 partials = Y[:,s,:] @ Ws ----------------
#define PT 8

__global__ __launch_bounds__(320) void k_pgemm(const float* __restrict__ convW,
                                               const float* __restrict__ W0) {
    int t0 = blockIdx.x * PT;
    int s = blockIdx.y;
    const float* W = (s == 0) ? W0 : (convW + (size_t)(s - 1) * DD * DD);
    int d = threadIdx.x;
    __shared__ float ys[PT][60];
    float acc[PT];
#pragma unroll
    for (int i = 0; i < PT; i++) acc[i] = 0.f;

    for (int c = 0; c < DD; c += 60) {
        __syncthreads();
        for (int l = threadIdx.x; l < PT * 60; l += 320) {
            int i = l / 60, j = l - (l / 60) * 60;
            ys[i][j] = g_Y[((size_t)(t0 + i) * 4 + s) * DD + c + j];
        }
        __syncthreads();
        if (d < DD) {
#pragma unroll 10
            for (int j = 0; j < 60; j++) {
                float w = W[(size_t)(c + j) * DD + d];
#pragma unroll
                for (int i = 0; i < PT; i++) acc[i] += ys[i][j] * w;
            }
        }
    }
    if (d < DD) {
#pragma unroll
        for (int i = 0; i < PT; i++)
            g_Ppart[((size_t)s * T_STEPS + t0 + i) * DD + d] = acc[i];
    }
}

// ---------------- kernel 3c: reduce U (16) and P0 (4) partials ----------------
__global__ void k_reduce2() {
    int i = blockIdx.x * blockDim.x + threadIdx.x;
    if (i < TD) {
        float s = 0.f;
#pragma unroll
        for (int p = 0; p < UKS; p++) s += g_Upart[(size_t)p * TD + i];
        g_U[i] = s;
        float q = 0.f;
#pragma unroll
        for (int p = 0; p < 4; p++) q += g_Ppart[(size_t)p * TD + i];
        g_P0[i] = q;
    }
}

// ---------------- kernel 4: recurrence, 4-CTA cluster, weights in registers --
// Each CTA owns 76 d's (4 x 76 >= 300+pad). 320 thr = 16 k-chunks x 20 d-quads
// (19 active). Weights fp32 in registers (80 floats/thread). m state (k=0..319,
// duplicated {m,m}) replicated in all 4 CTAs' smem, ping-pong buffers; gate
// phase broadcasts its 76 new m's to all CTAs via st.shared::cluster, one
// cluster barrier per step (release/acquire covers the DSMEM stores).
#define R4T 320

__global__ void __launch_bounds__(R4T, 1) __cluster_dims__(4, 1, 1)
k_recur4(const float* __restrict__ Uu) {
    __shared__ float mdup[2][2 * KP];   // [parity][2*k] = {m,m}
    __shared__ float vpf[16][80];       // partial v per k-chunk
    int tid = threadIdx.x;
    unsigned cta;
    asm("mov.u32 %0, %%cluster_ctarank;" : "=r"(cta));

    int kc = tid / 20;            // 0..15
    int dq = tid - kc * 20;       // 0..19
    bool act = (dq < 19);
    int k0 = kc * 20;
    int dg = (int)cta * 76 + dq * 4;   // global d of this thread's quad
    int dl4 = dq * 4;

    // ---- weights into registers: 20 k x 4 d as fp32 pairs ----
    unsigned long long wlo[20], whi[20];
#pragma unroll
    for (int j = 0; j < 20; j++) { wlo[j] = 0ULL; whi[j] = 0ULL; }
    if (act && dg < DD) {
#pragma unroll
        for (int j = 0; j < 20; j++) {
            int k = k0 + j;
            if (k < DD) {
                float4 w = *(const float4*)&Uu[(size_t)k * DD + dg];
                wlo[j] = pk64(__float_as_uint(w.x), __float_as_uint(w.y));
                whi[j] = pk64(__float_as_uint(w.z), __float_as_uint(w.w));
            }
        }
    }

    for (int i = tid; i < 2 * 2 * KP; i += R4T) ((float*)mdup)[i] = 0.f;
    __syncthreads();
    asm volatile("barrier.cluster.arrive.aligned;" ::: "memory");
    asm volatile("barrier.cluster.wait.aligned;" ::: "memory");

    // gate-phase mapping: thread i<76 handles global d = cta*76 + i
    int gi = tid;
    int gd = (int)cta * 76 + gi;
    bool gact = (gi < 76) && (gd < DD);
    uint32_t mbase[2];
    mbase[0] = smem_u32(&mdup[0][0]);
    mbase[1] = smem_u32(&mdup[1][0]);

    for (int t = 0; t < T_STEPS; t++) {
        int par = t & 1;
        float uval = 0.f, pval = 0.f;
        if (gact) {
            uval = g_U[(size_t)t * DD + gd];
            pval = g_P0[(size_t)t * DD + gd];
        }
        if (act) {
            const ulonglong2* mp = (const ulonglong2*)&mdup[par][2 * k0];
            unsigned long long acc0 = 0ULL, acc1 = 0ULL;
#pragma unroll
            for (int j = 0; j < 10; j++) {
                ulonglong2 mm = mp[j];
                fma2(acc0, wlo[2 * j], mm.x);
                fma2(acc1, whi[2 * j], mm.x);
                fma2(acc0, wlo[2 * j + 1], mm.y);
                fma2(acc1, whi[2 * j + 1], mm.y);
            }
            *(unsigned long long*)&vpf[kc][dl4] = acc0;
            *(unsigned long long*)&vpf[kc][dl4 + 2] = acc1;
        }
        __syncthreads();
        if (gact) {
            float v = 0.f;
#pragma unroll
            for (int c = 0; c < 16; c++) v += vpf[c][gi];
            float z = uval + v;
            float g = 1.f / (1.f + __expf(-z));
            float mold = mdup[par][2 * gd];
            float mn = mold + g * (pval - mold);
            unsigned long long md = pk64(__float_as_uint(mn), __float_as_uint(mn));
            uint32_t loff = mbase[par ^ 1] + (uint32_t)(8 * gd);
#pragma unroll
            for (unsigned r = 0; r < 4; r++) {
                uint32_t ra;
                asm("mapa.shared::cluster.u32 %0, %1, %2;" : "=r"(ra) : "r"(loff), "r"(r));
                asm volatile("st.shared::cluster.b64 [%0], %1;" :: "r"(ra), "l"(md) : "memory");
            }
            g_Hb[(size_t)t * KP + gd] = __float2bfloat16(fmaxf(mn, 0.f));
        }
        asm volatile("barrier.cluster.arrive.aligned;" ::: "memory");
        asm volatile("barrier.cluster.wait.aligned;" ::: "memory");
    }
}

// ---------------- kernel 5: logits via mma.sync bf16 (baseline PTX HMMA) -----
#define LPITCH 40

__device__ __forceinline__ void ldm_x4(uint32_t* f, uint32_t addr) {
    asm volatile("ldmatrix.sync.aligned.m8n8.x4.shared.b16 {%0,%1,%2,%3}, [%4];"
                 : "=r"(f[0]), "=r"(f[1]), "=r"(f[2]), "=r"(f[3]) : "r"(addr));
}
__device__ __forceinline__ void mma_bf16(float* c, const uint32_t* a,
                                         uint32_t b0, uint32_t b1) {
    asm volatile(
        "mma.sync.aligned.m16n8k16.row.col.f32.bf16.bf16.f32 "
        "{%0,%1,%2,%3}, {%4,%5,%6,%7}, {%8,%9}, {%0,%1,%2,%3};"
        : "+f"(c[0]), "+f"(c[1]), "+f"(c[2]), "+f"(c[3])
        : "r"(a[0]), "r"(a[1]), "r"(a[2]), "r"(a[3]), "r"(b0), "r"(b1));
}

__global__ __launch_bounds__(256) void k_logits_mma(const float* __restrict__ bg,
                                                    float* __restrict__ out) {
    __shared__ __align__(16) __nv_bfloat16 As[128 * LPITCH];
    __shared__ __align__(16) __nv_bfloat16 Bs[128 * LPITCH];
    int tid = threadIdx.x;
    int wid = tid >> 5, lane = tid & 31;
    int wm = wid & 1, wn = wid >> 1;
    int v0 = blockIdx.x * 128;
    int t0 = blockIdx.y * 128;

    float acc[4][4][4];
#pragma unroll
    for (int mt = 0; mt < 4; mt++)
#pragma unroll
        for (int nt = 0; nt < 4; nt++)
#pragma unroll
            for (int r = 0; r < 4; r++) acc[mt][nt][r] = 0.f;

    uint32_t sA = smem_u32(As), sB = smem_u32(Bs);
    int lrow = lane & 15;
    int lcol = (lane >> 4) << 3;

    for (int kb = 0; kb < KP; kb += 32) {
        __syncthreads();
#pragma unroll
        for (int h = 0; h < 2; h++) {
            int c = tid + h * 256;
            int r = c >> 2, q = c & 3;
            *(uint4*)(As + r * LPITCH + q * 8) =
                *(const uint4*)&g_Hb[(size_t)(t0 + r) * KP + kb + q * 8];
            *(uint4*)(Bs + r * LPITCH + q * 8) =
                *(const uint4*)&g_Wgb[(size_t)(v0 + r) * KP + kb + q * 8];
        }
        __syncthreads();
#pragma unroll
        for (int ks = 0; ks < 32; ks += 16) {
            uint32_t af[4][4], bf[2][4];
#pragma unroll
            for (int mt = 0; mt < 4; mt++)
                ldm_x4(af[mt],
                       sA + (uint32_t)(((wm * 64 + mt * 16 + lrow) * LPITCH + ks + lcol) * 2));
#pragma unroll
            for (int np = 0; np < 2; np++)
                ldm_x4(bf[np],
                       sB + (uint32_t)(((wn * 32 + np * 16 + lrow) * LPITCH + ks + lcol) * 2));
#pragma unroll
            for (int mt = 0; mt < 4; mt++) {
#pragma unroll
                for (int nt = 0; nt < 4; nt++) {
                    int np = nt >> 1, sub = nt & 1;
                    mma_bf16(acc[mt][nt], af[mt], bf[np][sub], bf[np][sub + 2]);
                }
            }
        }
    }

    int grp = lane >> 2, qc = (lane & 3) * 2;
#pragma unroll
    for (int nt = 0; nt < 4; nt++) {
        int v = v0 + wn * 32 + nt * 8 + qc;
        if (v >= VGN) continue;
        float b0 = bg[v], b1 = bg[v + 1];
#pragma unroll
        for (int mt = 0; mt < 4; mt++) {
            int t = t0 + wm * 64 + mt * 16 + grp;
            float2 o0 = make_float2(acc[mt][nt][0] + b0, acc[mt][nt][1] + b1);
            float2 o1 = make_float2(acc[mt][nt][2] + b0, acc[mt][nt][3] + b1);
            *(float2*)&out[(size_t)t * VGN + v] = o0;
            *(float2*)&out[(size_t)(t + 8) * VGN + v] = o1;
        }
    }
}

// ---------------- kernel 6: in-place log_softmax per row (f16x2 ex2) ---------
__global__ __launch_bounds__(512) void k_logsoftmax(float* __restrict__ out) {
    int t = blockIdx.x;
    float* row = out + (size_t)t * VGN;
    __shared__ float red[32];
    int tid = threadIdx.x;

    float m = -1e30f;
    for (int v = tid; v < VGN; v += blockDim.x) m = fmaxf(m, row[v]);
#pragma unroll
    for (int o = 16; o; o >>= 1) m = fmaxf(m, __shfl_xor_sync(~0u, m, o));
    if ((tid & 31) == 0) red[tid >> 5] = m;
    __syncthreads();
    if (tid < 32) {
        float x = (tid < (int)(blockDim.x >> 5)) ? red[tid] : -1e30f;
#pragma unroll
        for (int o = 16; o; o >>= 1) x = fmaxf(x, __shfl_xor_sync(~0u, x, o));
        if (tid == 0) red[0] = x;
    }
    __syncthreads();
    m = red[0];
    __syncthreads();

    // sum of exp via packed f16x2 ex2 (2 exps per MUFU op)
    const float L2E = 1.4426950408889634f;
    float mb = m * L2E;
    float s = 0.f;
    const float2* row2 = (const float2*)row;
    for (int v = tid; v < VGN / 2; v += blockDim.x) {
        float2 x = row2[v];
        float a = fmaf(x.x, L2E, -mb);
        float b = fmaf(x.y, L2E, -mb);
        unsigned h;
        asm("cvt.rn.f16x2.f32 %0, %1, %2;" : "=r"(h) : "f"(b), "f"(a));
        asm("ex2.approx.f16x2 %0, %0;" : "+r"(h));
        float lo, hi;
        asm("{.reg .f16 a,b; mov.b32 {a,b}, %2; cvt.f32.f16 %0, a; cvt.f32.f16 %1, b;}"
            : "=f"(lo), "=f"(hi) : "r"(h));
        s += lo + hi;
    }
#pragma unroll
    for (int o = 16; o; o >>= 1) s += __shfl_xor_sync(~0u, s, o);
    if ((tid & 31) == 0) red[tid >> 5] = s;
    __syncthreads();
    if (tid < 32) {
        float x = (tid < (int)(blockDim.x >> 5)) ? red[tid] : 0.f;
#pragma unroll
        for (int o = 16; o; o >>= 1) x += __shfl_xor_sync(~0u, x, o);
        if (tid == 0) red[0] = x;
    }
    __syncthreads();
    float lse = m + logf(red[0]);
    for (int v = tid; v < VGN; v += blockDim.x) row[v] -= lse;
}

// ---------------- tail zero (second ref output = zeros) ----------------
__global__ void k_zero(float* out, size_t start, size_t n) {
    size_t i = (size_t)blockIdx.x * blockDim.x + threadIdx.x;
    if (i < n) out[start + i] = 0.f;
}

extern "C" void kernel_launch(void* const* d_in, const int* in_sizes, int n_in,
                              void* d_out, int out_size) {
    const int*   xidx  = (const int*)d_in[0];
    const int*   esrc  = (const int*)d_in[1];
    const int*   edst  = (const int*)d_in[2];
    const float* X     = (const float*)d_in[3];
    const float* convW = (const float*)d_in[4];
    const float* W0    = (const float*)d_in[5];
    const float* Wu    = (const float*)d_in[6];
    const float* Uu    = (const float*)d_in[7];
    const float* Wg    = (const float*)d_in[8];
    const float* bg    = (const float*)d_in[9];
    float* out = (float*)d_out;

    k_gather<<<T_STEPS, 256>>>(xidx, X);
    {
        size_t nw = ((size_t)VP * KP) / 2;
        k_cvtW<<<(unsigned)((nw + 255) / 256), 256>>>(Wg);
    }
    k_padH<<<(T_STEPS * 20 + 255) / 256, 256>>>();
    k_ugemm<<<dim3(T_STEPS / UT, UKS), 320>>>(Wu);
    k_coefY<<<T_STEPS, 128>>>(esrc, edst);
    k_pgemm<<<dim3(T_STEPS / PT, 4), 320>>>(convW, W0);
    k_reduce2<<<(TD + 255) / 256, 256>>>();
    k_recur4<<<4, R4T>>>(Uu);
    k_logits_mma<<<dim3(VP / 128, T_STEPS / 128), 256>>>(bg, out);
    k_logsoftmax<<<T_STEPS, 512>>>(out);

    size_t used = (size_t)T_STEPS * VGN;
    if ((size_t)out_size > used) {
        size_t n = (size_t)out_size - used;
        k_zero<<<(unsigned)((n + 255) / 256), 256>>>(out, used, n);
    }
}

// round 7
// speedup vs baseline: 2.5856x; 1.1524x over previous
#include <cuda_runtime.h>
#include <cuda_bf16.h>
#include <cstdint>

#define T_STEPS 512
#define NN 32
#define DD 300
#define RR 3
#define EE 64
#define VGN 40000
#define KFLAT 9600   // NN*DD
#define TD (T_STEPS * DD)

#define KP 320       // padded K for logits GEMM (and recur k pad)
#define VP 40064     // padded V rows (313 x 128)
#define NP 384       // padded d for U/P tensor GEMMs (3 x 128)
#define KY 1280      // padded K for P GEMM (4 x 320)
#define UKS 30       // U k-splits (9600 / 320)
#define PKS 4        // P k-splits (1280 / 320)

// ---------------- scratch (device globals; no allocs allowed) ----------------
__device__ __nv_bfloat16 g_Xb[(size_t)T_STEPS * KFLAT]; // gathered x bf16
__device__ __nv_bfloat16 g_Wub[(size_t)NP * KFLAT];     // Wu^T bf16 [d][k]
__device__ __nv_bfloat16 g_Yb[(size_t)T_STEPS * KY];    // aggregated rows bf16
__device__ __nv_bfloat16 g_Wcatb[(size_t)NP * KY];      // [W0;convW]^T bf16
__device__ float g_UPp[(size_t)UKS * T_STEPS * NP];     // U split-k partials
__device__ float g_PPp[(size_t)PKS * T_STEPS * NP];     // P split-k partials
__device__ float g_U[(size_t)TD];                       // u_t
__device__ float g_P0[(size_t)TD];                      // proposed row 0 per t
__device__ __nv_bfloat16 g_Hb[(size_t)T_STEPS * KP];    // relu(mem0) bf16 padded
__device__ __nv_bfloat16 g_Wgb[(size_t)VP * KP];        // Wg bf16 padded

// ---------------- helpers ----------------
__device__ __forceinline__ unsigned long long pk64(unsigned a, unsigned b) {
    unsigned long long r;
    asm("mov.b64 %0, {%1, %2};" : "=l"(r) : "r"(a), "r"(b));
    return r;
}
__device__ __forceinline__ uint32_t smem_u32(const void* p) {
    uint32_t a;
    asm("{ .reg .u64 t; cvta.to.shared.u64 t, %1; cvt.u32.u64 %0, t; }" : "=r"(a) : "l"(p));
    return a;
}
__device__ __forceinline__ unsigned bf2pk(float a, float b) {
    return (unsigned)__bfloat16_as_ushort(__float2bfloat16(a)) |
           ((unsigned)__bfloat16_as_ushort(__float2bfloat16(b)) << 16);
}

// ---------------- kernel 1: gather x rows -> bf16 ----------------
__global__ void k_gather(const int* __restrict__ xidx, const float* __restrict__ X) {
    int t = blockIdx.x;
    __shared__ int ids[NN];
    if (threadIdx.x < NN) ids[threadIdx.x] = xidx[t * NN + threadIdx.x];
    __syncthreads();
    for (int i = threadIdx.x; i < KFLAT / 2; i += blockDim.x) {
        int e = 2 * i;
        int n = e / DD, k = e - n * DD;     // DD even -> pair stays in row
        const float* xr = X + (size_t)ids[n] * DD;
        *(unsigned*)&g_Xb[(size_t)t * KFLAT + e] = bf2pk(xr[k], xr[k + 1]);
    }
}

// ---------------- kernel 1b: Wg -> bf16 padded [VP][KP] ----------------
__global__ void k_cvtW(const float* __restrict__ Wg) {
    size_t i = ((size_t)blockIdx.x * blockDim.x + threadIdx.x) * 2;
    if (i >= (size_t)VP * KP) return;
    int v = (int)(i / KP), k = (int)(i - (size_t)v * KP);
    float a = (v < VGN && k < DD) ? Wg[(size_t)v * DD + k] : 0.f;
    float b = (v < VGN && k + 1 < DD) ? Wg[(size_t)v * DD + k + 1] : 0.f;
    *(unsigned*)&g_Wgb[i] = bf2pk(a, b);
}

// ---------------- kernel 1c: zero g_Hb pad columns [300,320) once ------------
__global__ void k_padH() {
    int i = blockIdx.x * blockDim.x + threadIdx.x;
    if (i < T_STEPS * 20) {
        int t = i / 20, k = 300 + (i - (i / 20) * 20);
        g_Hb[(size_t)t * KP + k] = __float2bfloat16(0.f);
    }
}

// ---------------- kernel 1d: Wu[k][d] -> Wub[d][k] bf16, d padded to NP ------
__global__ __launch_bounds__(1024) void k_trWu(const float* __restrict__ Wu) {
    __shared__ float smt[32][33];
    int k0 = blockIdx.x * 32, d0 = blockIdx.y * 32;
    int tx = threadIdx.x & 31, ty = threadIdx.x >> 5;
    int d = d0 + tx, k = k0 + ty;
    smt[ty][tx] = (d < DD) ? Wu[(size_t)k * DD + d] : 0.f;
    __syncthreads();
    // write Wub[(d0+ty)][k0+tx]
    g_Wub[(size_t)(d0 + ty) * KFLAT + k0 + tx] = __float2bfloat16(smt[tx][ty]);
}

// ---------------- kernel 1e: [W0;convW][k][d] -> Wcatb[d][k] bf16 ------------
__global__ __launch_bounds__(1024) void k_trWcat(const float* __restrict__ convW,
                                                 const float* __restrict__ W0) {
    __shared__ float smt[32][33];
    int k0 = blockIdx.x * 32, d0 = blockIdx.y * 32;
    int tx = threadIdx.x & 31, ty = threadIdx.x >> 5;
    int d = d0 + tx, k = k0 + ty;
    float v = 0.f;
    if (d < DD && k < 4 * DD) {
        int s = k / DD, kk = k - s * DD;
        const float* W = (s == 0) ? W0 : (convW + (size_t)(s - 1) * DD * DD);
        v = W[(size_t)kk * DD + d];
    }
    smt[ty][tx] = v;
    __syncthreads();
    g_Wcatb[(size_t)(d0 + ty) * KY + k0 + tx] = __float2bfloat16(smt[tx][ty]);
}

// ---------------- kernel 3a: per-t coefficients + aggregated rows Y (bf16) ---
__global__ __launch_bounds__(128) void k_coefY(const int* __restrict__ esrc,
                                               const int* __restrict__ edst) {
    int t = blockIdx.x;
    int tid = threadIdx.x;
    __shared__ int cnt[RR][NN];
    __shared__ float dinv[RR][NN];
    __shared__ float cval[RR][NN + 1];
    __shared__ int cidx[RR][NN + 1];
    __shared__ int cn[RR];

    if (tid < RR * NN) cnt[tid / NN][tid % NN] = 0;
    __syncthreads();

    const int* es = esrc + (size_t)t * RR * EE;
    const int* ed = edst + (size_t)t * RR * EE;
    for (int j = tid; j < RR * EE; j += 128)
        atomicAdd(&cnt[j / EE][ed[j]], 1);   // integer atomics: deterministic
    __syncthreads();

    if (tid < RR * NN) {
        int r = tid / NN, n = tid % NN;
        dinv[r][n] = rsqrtf((float)(cnt[r][n] + 1));
    }
    __syncthreads();

    if (tid < RR) {
        int r = tid;
        float c[NN];
#pragma unroll
        for (int n = 0; n < NN; n++) c[n] = 0.f;
        for (int e = 0; e < EE; e++) {
            if (ed[r * EE + e] == 0) {
                int s = es[r * EE + e];
                c[s] += dinv[r][s];
            }
        }
        float d0 = dinv[r][0];
        c[0] += d0;
        int m = 0;
        for (int n = 0; n < NN; n++) {
            if (c[n] != 0.f) { cidx[r][m] = n; cval[r][m] = c[n] * d0; m++; }
        }
        cn[r] = m;
    }
    __syncthreads();

    const __nv_bfloat16* xg = g_Xb + (size_t)t * KFLAT;
    __nv_bfloat16* Yt = g_Yb + (size_t)t * KY;
    for (int k = tid; k < DD; k += 128) {
        Yt[k] = xg[k];   // s=0: x0
#pragma unroll
        for (int r = 0; r < RR; r++) {
            float a = 0.f;
            int m = cn[r];
            for (int q = 0; q < m; q++)
                a += cval[r][q] * __bfloat162float(xg[cidx[r][q] * DD + k]);
            Yt[(r + 1) * DD + k] = __float2bfloat16(a);
        }
    }
    if (tid < KY - 4 * DD)  // zero pad [1200, 1280)
        Yt[4 * DD + tid] = __float2bfloat16(0.f);
}

// ---------------- shared mma tile machinery ----------------
#define LPITCH 40

__device__ __forceinline__ void ldm_x4(uint32_t* f, uint32_t addr) {
    asm volatile("ldmatrix.sync.aligned.m8n8.x4.shared.b16 {%0,%1,%2,%3}, [%4];"
                 : "=r"(f[0]), "=r"(f[1]), "=r"(f[2]), "=r"(f[3]) : "r"(addr));
}
__device__ __forceinline__ void mma_bf16(float* c, const uint32_t* a,
                                         uint32_t b0, uint32_t b1) {
    asm volatile(
        "mma.sync.aligned.m16n8k16.row.col.f32.bf16.bf16.f32 "
        "{%0,%1,%2,%3}, {%4,%5,%6,%7}, {%8,%9}, {%0,%1,%2,%3};"
        : "+f"(c[0]), "+f"(c[1]), "+f"(c[2]), "+f"(c[3])
        : "r"(a[0]), "r"(a[1]), "r"(a[2]), "r"(a[3]), "r"(b0), "r"(b1));
}

// ---------------- kernel 2: split-K bf16 tensor GEMM (U and P paths) ---------
// mode 0: U partials = Xb[512,9600] @ Wub[384,9600]^T   (z = 30 k-splits)
// mode 1: P partials = Yb[512,1280] @ Wcatb[384,1280]^T (z = 4 k-splits)
__global__ __launch_bounds__(256) void k_tcgemm(int mode) {
    const __nv_bfloat16* A = mode ? g_Yb : g_Xb;
    const __nv_bfloat16* B = mode ? g_Wcatb : g_Wub;
    float* outp = mode ? g_PPp : g_UPp;
    int kstr = mode ? KY : KFLAT;

    __shared__ __align__(16) __nv_bfloat16 As[128 * LPITCH];
    __shared__ __align__(16) __nv_bfloat16 Bs[128 * LPITCH];
    int tid = threadIdx.x;
    int wid = tid >> 5, lane = tid & 31;
    int wm = wid & 1, wn = wid >> 1;
    int v0 = blockIdx.x * 128;
    int t0 = blockIdx.y * 128;
    int kb0 = blockIdx.z * 320;

    float acc[4][4][4];
#pragma unroll
    for (int mt = 0; mt < 4; mt++)
#pragma unroll
        for (int nt = 0; nt < 4; nt++)
#pragma unroll
            for (int r = 0; r < 4; r++) acc[mt][nt][r] = 0.f;

    uint32_t sA = smem_u32(As), sB = smem_u32(Bs);
    int lrow = lane & 15;
    int lcol = (lane >> 4) << 3;

    for (int kb = 0; kb < 320; kb += 32) {
        __syncthreads();
#pragma unroll
        for (int h = 0; h < 2; h++) {
            int c = tid + h * 256;
            int r = c >> 2, q = c & 3;
            *(uint4*)(As + r * LPITCH + q * 8) =
                *(const uint4*)&A[(size_t)(t0 + r) * kstr + kb0 + kb + q * 8];
            *(uint4*)(Bs + r * LPITCH + q * 8) =
                *(const uint4*)&B[(size_t)(v0 + r) * kstr + kb0 + kb + q * 8];
        }
        __syncthreads();
#pragma unroll
        for (int ks = 0; ks < 32; ks += 16) {
            uint32_t af[4][4], bfr[2][4];
#pragma unroll
            for (int mt = 0; mt < 4; mt++)
                ldm_x4(af[mt],
                       sA + (uint32_t)(((wm * 64 + mt * 16 + lrow) * LPITCH + ks + lcol) * 2));
#pragma unroll
            for (int np = 0; np < 2; np++)
                ldm_x4(bfr[np],
                       sB + (uint32_t)(((wn * 32 + np * 16 + lrow) * LPITCH + ks + lcol) * 2));
#pragma unroll
            for (int mt = 0; mt < 4; mt++) {
#pragma unroll
                for (int nt = 0; nt < 4; nt++) {
                    int np = nt >> 1, sub = nt & 1;
                    mma_bf16(acc[mt][nt], af[mt], bfr[np][sub], bfr[np][sub + 2]);
                }
            }
        }
    }

    float* outz = outp + (size_t)blockIdx.z * T_STEPS * NP;
    int grp = lane >> 2, qc = (lane & 3) * 2;
#pragma unroll
    for (int nt = 0; nt < 4; nt++) {
        int v = v0 + wn * 32 + nt * 8 + qc;
#pragma unroll
        for (int mt = 0; mt < 4; mt++) {
            int t = t0 + wm * 64 + mt * 16 + grp;
            *(float2*)&outz[(size_t)t * NP + v] =
                make_float2(acc[mt][nt][0], acc[mt][nt][1]);
            *(float2*)&outz[(size_t)(t + 8) * NP + v] =
                make_float2(acc[mt][nt][2], acc[mt][nt][3]);
        }
    }
}

// ---------------- kernel 3c: reduce U (30) and P0 (4) partials ----------------
__global__ void k_reduce2() {
    int i = blockIdx.x * blockDim.x + threadIdx.x;
    if (i < TD) {
        int t = i / DD, d = i - (i / DD) * DD;
        float s = 0.f;
#pragma unroll
        for (int p = 0; p < UKS; p++) s += g_UPp[((size_t)p * T_STEPS + t) * NP + d];
        g_U[i] = s;
        float q = 0.f;
#pragma unroll
        for (int p = 0; p < PKS; p++) q += g_PPp[((size_t)p * T_STEPS + t) * NP + d];
        g_P0[i] = q;
    }
}

// ---------------- kernel 4: recurrence, 4-CTA cluster, weights in registers --
#define R4T 320

__device__ __forceinline__ void fma2(unsigned long long& acc,
                                     unsigned long long a,
                                     unsigned long long b) {
    asm("fma.rn.f32x2 %0, %1, %2, %0;" : "+l"(acc) : "l"(a), "l"(b));
}

__global__ void __launch_bounds__(R4T, 1) __cluster_dims__(4, 1, 1)
k_recur4(const float* __restrict__ Uu) {
    __shared__ float mdup[2][2 * KP];   // [parity][2*k] = {m,m}
    __shared__ float vpf[16][80];       // partial v per k-chunk
    int tid = threadIdx.x;
    unsigned cta;
    asm("mov.u32 %0, %%cluster_ctarank;" : "=r"(cta));

    int kc = tid / 20;            // 0..15
    int dq = tid - kc * 20;       // 0..19
    bool act = (dq < 19);
    int k0 = kc * 20;
    int dg = (int)cta * 76 + dq * 4;
    int dl4 = dq * 4;

    unsigned long long wlo[20], whi[20];
#pragma unroll
    for (int j = 0; j < 20; j++) { wlo[j] = 0ULL; whi[j] = 0ULL; }
    if (act && dg < DD) {
#pragma unroll
        for (int j = 0; j < 20; j++) {
            int k = k0 + j;
            if (k < DD) {
                float4 w = *(const float4*)&Uu[(size_t)k * DD + dg];
                wlo[j] = pk64(__float_as_uint(w.x), __float_as_uint(w.y));
                whi[j] = pk64(__float_as_uint(w.z), __float_as_uint(w.w));
            }
        }
    }

    for (int i = tid; i < 2 * 2 * KP; i += R4T) ((float*)mdup)[i] = 0.f;
    __syncthreads();
    asm volatile("barrier.cluster.arrive.aligned;" ::: "memory");
    asm volatile("barrier.cluster.wait.aligned;" ::: "memory");

    int gi = tid;
    int gd = (int)cta * 76 + gi;
    bool gact = (gi < 76) && (gd < DD);
    uint32_t mbase[2];
    mbase[0] = smem_u32(&mdup[0][0]);
    mbase[1] = smem_u32(&mdup[1][0]);

    for (int t = 0; t < T_STEPS; t++) {
        int par = t & 1;
        float uval = 0.f, pval = 0.f;
        if (gact) {
            uval = g_U[(size_t)t * DD + gd];
            pval = g_P0[(size_t)t * DD + gd];
        }
        if (act) {
            const ulonglong2* mp = (const ulonglong2*)&mdup[par][2 * k0];
            unsigned long long acc0 = 0ULL, acc1 = 0ULL;
#pragma unroll
            for (int j = 0; j < 10; j++) {
                ulonglong2 mm = mp[j];
                fma2(acc0, wlo[2 * j], mm.x);
                fma2(acc1, whi[2 * j], mm.x);
                fma2(acc0, wlo[2 * j + 1], mm.y);
                fma2(acc1, whi[2 * j + 1], mm.y);
            }
            *(unsigned long long*)&vpf[kc][dl4] = acc0;
            *(unsigned long long*)&vpf[kc][dl4 + 2] = acc1;
        }
        __syncthreads();
        if (gact) {
            float v = 0.f;
#pragma unroll
            for (int c = 0; c < 16; c++) v += vpf[c][gi];
            float z = uval + v;
            float g = 1.f / (1.f + __expf(-z));
            float mold = mdup[par][2 * gd];
            float mn = mold + g * (pval - mold);
            unsigned long long md = pk64(__float_as_uint(mn), __float_as_uint(mn));
            uint32_t loff = mbase[par ^ 1] + (uint32_t)(8 * gd);
#pragma unroll
            for (unsigned r = 0; r < 4; r++) {
                uint32_t ra;
                asm("mapa.shared::cluster.u32 %0, %1, %2;" : "=r"(ra) : "r"(loff), "r"(r));
                asm volatile("st.shared::cluster.b64 [%0], %1;" :: "r"(ra), "l"(md) : "memory");
            }
            g_Hb[(size_t)t * KP + gd] = __float2bfloat16(fmaxf(mn, 0.f));
        }
        asm volatile("barrier.cluster.arrive.aligned;" ::: "memory");
        asm volatile("barrier.cluster.wait.aligned;" ::: "memory");
    }
}

// ---------------- kernel 5: logits via mma.sync bf16 ----------------
__global__ __launch_bounds__(256) void k_logits_mma(const float* __restrict__ bg,
                                                    float* __restrict__ out) {
    __shared__ __align__(16) __nv_bfloat16 As[128 * LPITCH];
    __shared__ __align__(16) __nv_bfloat16 Bs[128 * LPITCH];
    int tid = threadIdx.x;
    int wid = tid >> 5, lane = tid & 31;
    int wm = wid & 1, wn = wid >> 1;
    int v0 = blockIdx.x * 128;
    int t0 = blockIdx.y * 128;

    float acc[4][4][4];
#pragma unroll
    for (int mt = 0; mt < 4; mt++)
#pragma unroll
        for (int nt = 0; nt < 4; nt++)
#pragma unroll
            for (int r = 0; r < 4; r++) acc[mt][nt][r] = 0.f;

    uint32_t sA = smem_u32(As), sB = smem_u32(Bs);
    int lrow = lane & 15;
    int lcol = (lane >> 4) << 3;

    for (int kb = 0; kb < KP; kb += 32) {
        __syncthreads();
#pragma unroll
        for (int h = 0; h < 2; h++) {
            int c = tid + h * 256;
            int r = c >> 2, q = c & 3;
            *(uint4*)(As + r * LPITCH + q * 8) =
                *(const uint4*)&g_Hb[(size_t)(t0 + r) * KP + kb + q * 8];
            *(uint4*)(Bs + r * LPITCH + q * 8) =
                *(const uint4*)&g_Wgb[(size_t)(v0 + r) * KP + kb + q * 8];
        }
        __syncthreads();
#pragma unroll
        for (int ks = 0; ks < 32; ks += 16) {
            uint32_t af[4][4], bfr[2][4];
#pragma unroll
            for (int mt = 0; mt < 4; mt++)
                ldm_x4(af[mt],
                       sA + (uint32_t)(((wm * 64 + mt * 16 + lrow) * LPITCH + ks + lcol) * 2));
#pragma unroll
            for (int np = 0; np < 2; np++)
                ldm_x4(bfr[np],
                       sB + (uint32_t)(((wn * 32 + np * 16 + lrow) * LPITCH + ks + lcol) * 2));
#pragma unroll
            for (int mt = 0; mt < 4; mt++) {
#pragma unroll
                for (int nt = 0; nt < 4; nt++) {
                    int np = nt >> 1, sub = nt & 1;
                    mma_bf16(acc[mt][nt], af[mt], bfr[np][sub], bfr[np][sub + 2]);
                }
            }
        }
    }

    int grp = lane >> 2, qc = (lane & 3) * 2;
#pragma unroll
    for (int nt = 0; nt < 4; nt++) {
        int v = v0 + wn * 32 + nt * 8 + qc;
        if (v >= VGN) continue;
        float b0 = bg[v], b1 = bg[v + 1];
#pragma unroll
        for (int mt = 0; mt < 4; mt++) {
            int t = t0 + wm * 64 + mt * 16 + grp;
            float2 o0 = make_float2(acc[mt][nt][0] + b0, acc[mt][nt][1] + b1);
            float2 o1 = make_float2(acc[mt][nt][2] + b0, acc[mt][nt][3] + b1);
            *(float2*)&out[(size_t)t * VGN + v] = o0;
            *(float2*)&out[(size_t)(t + 8) * VGN + v] = o1;
        }
    }
}

// ---------------- kernel 6: in-place log_softmax per row (f16x2 ex2) ---------
__global__ __launch_bounds__(512) void k_logsoftmax(float* __restrict__ out) {
    int t = blockIdx.x;
    float* row = out + (size_t)t * VGN;
    __shared__ float red[32];
    int tid = threadIdx.x;

    float m = -1e30f;
    for (int v = tid; v < VGN; v += blockDim.x) m = fmaxf(m, row[v]);
#pragma unroll
    for (int o = 16; o; o >>= 1) m = fmaxf(m, __shfl_xor_sync(~0u, m, o));
    if ((tid & 31) == 0) red[tid >> 5] = m;
    __syncthreads();
    if (tid < 32) {
        float x = (tid < (int)(blockDim.x >> 5)) ? red[tid] : -1e30f;
#pragma unroll
        for (int o = 16; o; o >>= 1) x = fmaxf(x, __shfl_xor_sync(~0u, x, o));
        if (tid == 0) red[0] = x;
    }
    __syncthreads();
    m = red[0];
    __syncthreads();

    const float L2E = 1.4426950408889634f;
    float mb = m * L2E;
    float s = 0.f;
    const float2* row2 = (const float2*)row;
    for (int v = tid; v < VGN / 2; v += blockDim.x) {
        float2 x = row2[v];
        float a = fmaf(x.x, L2E, -mb);
        float b = fmaf(x.y, L2E, -mb);
        unsigned h;
        asm("cvt.rn.f16x2.f32 %0, %1, %2;" : "=r"(h) : "f"(b), "f"(a));
        asm("ex2.approx.f16x2 %0, %0;" : "+r"(h));
        float lo, hi;
        asm("{.reg .f16 a,b; mov.b32 {a,b}, %2; cvt.f32.f16 %0, a; cvt.f32.f16 %1, b;}"
            : "=f"(lo), "=f"(hi) : "r"(h));
        s += lo + hi;
    }
#pragma unroll
    for (int o = 16; o; o >>= 1) s += __shfl_xor_sync(~0u, s, o);
    if ((tid & 31) == 0) red[tid >> 5] = s;
    __syncthreads();
    if (tid < 32) {
        float x = (tid < (int)(blockDim.x >> 5)) ? red[tid] : 0.f;
#pragma unroll
        for (int o = 16; o; o >>= 1) x += __shfl_xor_sync(~0u, x, o);
        if (tid == 0) red[0] = x;
    }
    __syncthreads();
    float lse = m + logf(red[0]);
    for (int v = tid; v < VGN; v += blockDim.x) row[v] -= lse;
}

// ---------------- tail zero (second ref output = zeros) ----------------
__global__ void k_zero(float* out, size_t start, size_t n) {
    size_t i = (size_t)blockIdx.x * blockDim.x + threadIdx.x;
    if (i < n) out[start + i] = 0.f;
}

extern "C" void kernel_launch(void* const* d_in, const int* in_sizes, int n_in,
                              void* d_out, int out_size) {
    const int*   xidx  = (const int*)d_in[0];
    const int*   esrc  = (const int*)d_in[1];
    const int*   edst  = (const int*)d_in[2];
    const float* X     = (const float*)d_in[3];
    const float* convW = (const float*)d_in[4];
    const float* W0    = (const float*)d_in[5];
    const float* Wu    = (const float*)d_in[6];
    const float* Uu    = (const float*)d_in[7];
    const float* Wg    = (const float*)d_in[8];
    const float* bg    = (const float*)d_in[9];
    float* out = (float*)d_out;

    k_gather<<<T_STEPS, 256>>>(xidx, X);
    {
        size_t nw = ((size_t)VP * KP) / 2;
        k_cvtW<<<(unsigned)((nw + 255) / 256), 256>>>(Wg);
    }
    k_padH<<<(T_STEPS * 20 + 255) / 256, 256>>>();
    k_trWu<<<dim3(KFLAT / 32, NP / 32), 1024>>>(Wu);
    k_trWcat<<<dim3(KY / 32, NP / 32), 1024>>>(convW, W0);
    k_coefY<<<T_STEPS, 128>>>(esrc, edst);
    k_tcgemm<<<dim3(3, 4, UKS), 256>>>(0);   // U partials
    k_tcgemm<<<dim3(3, 4, PKS), 256>>>(1);   // P partials
    k_reduce2<<<(TD + 255) / 256, 256>>>();
    k_recur4<<<4, R4T>>>(Uu);
    k_logits_mma<<<dim3(VP / 128, T_STEPS / 128), 256>>>(bg, out);
    k_logsoftmax<<<T_STEPS, 512>>>(out);

    size_t used = (size_t)T_STEPS * VGN;
    if ((size_t)out_size > used) {
        size_t n = (size_t)out_size - used;
        k_zero<<<(unsigned)((n + 255) / 256), 256>>>(out, used, n);
    }
}

// round 8
// speedup vs baseline: 2.8654x; 1.1082x over previous
#include <cuda_runtime.h>
#include <cuda_bf16.h>
#include <cstdint>

#define T_STEPS 512
#define NN 32
#define DD 300
#define RR 3
#define EE 64
#define VGN 40000
#define KFLAT 9600   // NN*DD
#define TD (T_STEPS * DD)

#define KP 320       // padded K for logits GEMM (and recur k pad)
#define VP 40064     // padded V rows (313 x 128)
#define NP 384       // padded d for U/P tensor GEMMs (3 x 128)
#define KY 1280      // padded K for P GEMM (4 x 320)
#define UKS 30       // U k-splits (9600 / 320)
#define PKS 4        // P k-splits (1280 / 320)

// ---------------- scratch (device globals; no allocs allowed) ----------------
__device__ __nv_bfloat16 g_Xb[(size_t)T_STEPS * KFLAT]; // gathered x bf16
__device__ __nv_bfloat16 g_Wub[(size_t)NP * KFLAT];     // Wu^T bf16 [d][k]
__device__ __nv_bfloat16 g_Yb[(size_t)T_STEPS * KY];    // aggregated rows bf16
__device__ __nv_bfloat16 g_Wcatb[(size_t)NP * KY];      // [W0;convW]^T bf16
__device__ float g_UPp[(size_t)UKS * T_STEPS * NP];     // U split-k partials
__device__ float g_PPp[(size_t)PKS * T_STEPS * NP];     // P split-k partials
__device__ float g_U[(size_t)TD];                       // u_t
__device__ float g_P0[(size_t)TD];                      // proposed row 0 per t
__device__ __nv_bfloat16 g_Hb[(size_t)T_STEPS * KP];    // relu(mem0) bf16 padded
__device__ __nv_bfloat16 g_Wgb[(size_t)VP * KP];        // Wg bf16 padded

// ---------------- helpers ----------------
__device__ __forceinline__ unsigned long long pk64(unsigned a, unsigned b) {
    unsigned long long r;
    asm("mov.b64 %0, {%1, %2};" : "=l"(r) : "r"(a), "r"(b));
    return r;
}
__device__ __forceinline__ uint32_t smem_u32(const void* p) {
    uint32_t a;
    asm("{ .reg .u64 t; cvta.to.shared.u64 t, %1; cvt.u32.u64 %0, t; }" : "=r"(a) : "l"(p));
    return a;
}
__device__ __forceinline__ unsigned bf2pk(float a, float b) {
    return (unsigned)__bfloat16_as_ushort(__float2bfloat16(a)) |
           ((unsigned)__bfloat16_as_ushort(__float2bfloat16(b)) << 16);
}
__device__ __forceinline__ void fma2(unsigned long long& acc,
                                     unsigned long long a,
                                     unsigned long long b) {
    asm("fma.rn.f32x2 %0, %1, %2, %0;" : "+l"(acc) : "l"(a), "l"(b));
}

// ---------------- kernel 1: gather x rows -> bf16 ----------------
__global__ void k_gather(const int* __restrict__ xidx, const float* __restrict__ X) {
    int t = blockIdx.x;
    __shared__ int ids[NN];
    if (threadIdx.x < NN) ids[threadIdx.x] = xidx[t * NN + threadIdx.x];
    __syncthreads();
    for (int i = threadIdx.x; i < KFLAT / 2; i += blockDim.x) {
        int e = 2 * i;
        int n = e / DD, k = e - n * DD;     // DD even -> pair stays in row
        const float* xr = X + (size_t)ids[n] * DD;
        *(unsigned*)&g_Xb[(size_t)t * KFLAT + e] = bf2pk(xr[k], xr[k + 1]);
    }
}

// ---------------- kernel 1b: Wg -> bf16 padded [VP][KP] ----------------
__global__ void k_cvtW(const float* __restrict__ Wg) {
    size_t i = ((size_t)blockIdx.x * blockDim.x + threadIdx.x) * 2;
    if (i >= (size_t)VP * KP) return;
    int v = (int)(i / KP), k = (int)(i - (size_t)v * KP);
    float a = (v < VGN && k < DD) ? Wg[(size_t)v * DD + k] : 0.f;
    float b = (v < VGN && k + 1 < DD) ? Wg[(size_t)v * DD + k + 1] : 0.f;
    *(unsigned*)&g_Wgb[i] = bf2pk(a, b);
}

// ---------------- kernel 1c: zero g_Hb pad columns [300,320) once ------------
__global__ void k_padH() {
    int i = blockIdx.x * blockDim.x + threadIdx.x;
    if (i < T_STEPS * 20) {
        int t = i / 20, k = 300 + (i - (i / 20) * 20);
        g_Hb[(size_t)t * KP + k] = __float2bfloat16(0.f);
    }
}

// ---------------- kernel 1d: Wu[k][d] -> Wub[d][k] bf16, d padded to NP ------
__global__ __launch_bounds__(1024) void k_trWu(const float* __restrict__ Wu) {
    __shared__ float smt[32][33];
    int k0 = blockIdx.x * 32, d0 = blockIdx.y * 32;
    int tx = threadIdx.x & 31, ty = threadIdx.x >> 5;
    int d = d0 + tx, k = k0 + ty;
    smt[ty][tx] = (d < DD) ? Wu[(size_t)k * DD + d] : 0.f;
    __syncthreads();
    g_Wub[(size_t)(d0 + ty) * KFLAT + k0 + tx] = __float2bfloat16(smt[tx][ty]);
}

// ---------------- kernel 1e: [W0;convW][k][d] -> Wcatb[d][k] bf16 ------------
__global__ __launch_bounds__(1024) void k_trWcat(const float* __restrict__ convW,
                                                 const float* __restrict__ W0) {
    __shared__ float smt[32][33];
    int k0 = blockIdx.x * 32, d0 = blockIdx.y * 32;
    int tx = threadIdx.x & 31, ty = threadIdx.x >> 5;
    int d = d0 + tx, k = k0 + ty;
    float v = 0.f;
    if (d < DD && k < 4 * DD) {
        int s = k / DD, kk = k - s * DD;
        const float* W = (s == 0) ? W0 : (convW + (size_t)(s - 1) * DD * DD);
        v = W[(size_t)kk * DD + d];
    }
    smt[ty][tx] = v;
    __syncthreads();
    g_Wcatb[(size_t)(d0 + ty) * KY + k0 + tx] = __float2bfloat16(smt[tx][ty]);
}

// ---------------- kernel 3a: per-t coefficients + aggregated rows Y (bf16) ---
__global__ __launch_bounds__(128) void k_coefY(const int* __restrict__ esrc,
                                               const int* __restrict__ edst) {
    int t = blockIdx.x;
    int tid = threadIdx.x;
    __shared__ int cnt[RR][NN];
    __shared__ float dinv[RR][NN];
    __shared__ float cval[RR][NN + 1];
    __shared__ int cidx[RR][NN + 1];
    __shared__ int cn[RR];

    if (tid < RR * NN) cnt[tid / NN][tid % NN] = 0;
    __syncthreads();

    const int* es = esrc + (size_t)t * RR * EE;
    const int* ed = edst + (size_t)t * RR * EE;
    for (int j = tid; j < RR * EE; j += 128)
        atomicAdd(&cnt[j / EE][ed[j]], 1);   // integer atomics: deterministic
    __syncthreads();

    if (tid < RR * NN) {
        int r = tid / NN, n = tid % NN;
        dinv[r][n] = rsqrtf((float)(cnt[r][n] + 1));
    }
    __syncthreads();

    if (tid < RR) {
        int r = tid;
        float c[NN];
#pragma unroll
        for (int n = 0; n < NN; n++) c[n] = 0.f;
        for (int e = 0; e < EE; e++) {
            if (ed[r * EE + e] == 0) {
                int s = es[r * EE + e];
                c[s] += dinv[r][s];
            }
        }
        float d0 = dinv[r][0];
        c[0] += d0;
        int m = 0;
        for (int n = 0; n < NN; n++) {
            if (c[n] != 0.f) { cidx[r][m] = n; cval[r][m] = c[n] * d0; m++; }
        }
        cn[r] = m;
    }
    __syncthreads();

    const __nv_bfloat16* xg = g_Xb + (size_t)t * KFLAT;
    __nv_bfloat16* Yt = g_Yb + (size_t)t * KY;
    for (int k = tid; k < DD; k += 128) {
        Yt[k] = xg[k];   // s=0: x0
#pragma unroll
        for (int r = 0; r < RR; r++) {
            float a = 0.f;
            int m = cn[r];
            for (int q = 0; q < m; q++)
                a += cval[r][q] * __bfloat162float(xg[cidx[r][q] * DD + k]);
            Yt[(r + 1) * DD + k] = __float2bfloat16(a);
        }
    }
    if (tid < KY - 4 * DD)  // zero pad [1200, 1280)
        Yt[4 * DD + tid] = __float2bfloat16(0.f);
}

// ---------------- shared mma tile machinery ----------------
#define LPITCH 40

__device__ __forceinline__ void ldm_x4(uint32_t* f, uint32_t addr) {
    asm volatile("ldmatrix.sync.aligned.m8n8.x4.shared.b16 {%0,%1,%2,%3}, [%4];"
                 : "=r"(f[0]), "=r"(f[1]), "=r"(f[2]), "=r"(f[3]) : "r"(addr));
}
__device__ __forceinline__ void mma_bf16(float* c, const uint32_t* a,
                                         uint32_t b0, uint32_t b1) {
    asm volatile(
        "mma.sync.aligned.m16n8k16.row.col.f32.bf16.bf16.f32 "
        "{%0,%1,%2,%3}, {%4,%5,%6,%7}, {%8,%9}, {%0,%1,%2,%3};"
        : "+f"(c[0]), "+f"(c[1]), "+f"(c[2]), "+f"(c[3])
        : "r"(a[0]), "r"(a[1]), "r"(a[2]), "r"(a[3]), "r"(b0), "r"(b1));
}

// ---------------- kernel 2: split-K bf16 tensor GEMM (U and P paths) ---------
__global__ __launch_bounds__(256) void k_tcgemm(int mode) {
    const __nv_bfloat16* A = mode ? g_Yb : g_Xb;
    const __nv_bfloat16* B = mode ? g_Wcatb : g_Wub;
    float* outp = mode ? g_PPp : g_UPp;
    int kstr = mode ? KY : KFLAT;

    __shared__ __align__(16) __nv_bfloat16 As[128 * LPITCH];
    __shared__ __align__(16) __nv_bfloat16 Bs[128 * LPITCH];
    int tid = threadIdx.x;
    int wid = tid >> 5, lane = tid & 31;
    int wm = wid & 1, wn = wid >> 1;
    int v0 = blockIdx.x * 128;
    int t0 = blockIdx.y * 128;
    int kb0 = blockIdx.z * 320;

    float acc[4][4][4];
#pragma unroll
    for (int mt = 0; mt < 4; mt++)
#pragma unroll
        for (int nt = 0; nt < 4; nt++)
#pragma unroll
            for (int r = 0; r < 4; r++) acc[mt][nt][r] = 0.f;

    uint32_t sA = smem_u32(As), sB = smem_u32(Bs);
    int lrow = lane & 15;
    int lcol = (lane >> 4) << 3;

    for (int kb = 0; kb < 320; kb += 32) {
        __syncthreads();
#pragma unroll
        for (int h = 0; h < 2; h++) {
            int c = tid + h * 256;
            int r = c >> 2, q = c & 3;
            *(uint4*)(As + r * LPITCH + q * 8) =
                *(const uint4*)&A[(size_t)(t0 + r) * kstr + kb0 + kb + q * 8];
            *(uint4*)(Bs + r * LPITCH + q * 8) =
                *(const uint4*)&B[(size_t)(v0 + r) * kstr + kb0 + kb + q * 8];
        }
        __syncthreads();
#pragma unroll
        for (int ks = 0; ks < 32; ks += 16) {
            uint32_t af[4][4], bfr[2][4];
#pragma unroll
            for (int mt = 0; mt < 4; mt++)
                ldm_x4(af[mt],
                       sA + (uint32_t)(((wm * 64 + mt * 16 + lrow) * LPITCH + ks + lcol) * 2));
#pragma unroll
            for (int np = 0; np < 2; np++)
                ldm_x4(bfr[np],
                       sB + (uint32_t)(((wn * 32 + np * 16 + lrow) * LPITCH + ks + lcol) * 2));
#pragma unroll
            for (int mt = 0; mt < 4; mt++) {
#pragma unroll
                for (int nt = 0; nt < 4; nt++) {
                    int np = nt >> 1, sub = nt & 1;
                    mma_bf16(acc[mt][nt], af[mt], bfr[np][sub], bfr[np][sub + 2]);
                }
            }
        }
    }

    float* outz = outp + (size_t)blockIdx.z * T_STEPS * NP;
    int grp = lane >> 2, qc = (lane & 3) * 2;
#pragma unroll
    for (int nt = 0; nt < 4; nt++) {
        int v = v0 + wn * 32 + nt * 8 + qc;
#pragma unroll
        for (int mt = 0; mt < 4; mt++) {
            int t = t0 + wm * 64 + mt * 16 + grp;
            *(float2*)&outz[(size_t)t * NP + v] =
                make_float2(acc[mt][nt][0], acc[mt][nt][1]);
            *(float2*)&outz[(size_t)(t + 8) * NP + v] =
                make_float2(acc[mt][nt][2], acc[mt][nt][3]);
        }
    }
}

// ---------------- kernel 3c: reduce U (30) and P0 (4) partials ----------------
__global__ void k_reduce2() {
    int i = blockIdx.x * blockDim.x + threadIdx.x;
    if (i < TD) {
        int t = i / DD, d = i - (i / DD) * DD;
        float s = 0.f;
#pragma unroll
        for (int p = 0; p < UKS; p++) s += g_UPp[((size_t)p * T_STEPS + t) * NP + d];
        g_U[i] = s;
        float q = 0.f;
#pragma unroll
        for (int p = 0; p < PKS; p++) q += g_PPp[((size_t)p * T_STEPS + t) * NP + d];
        g_P0[i] = q;
    }
}

// ---------------- kernel 4: recurrence, 8-CTA cluster, weights in registers --
// CTA c owns d in [c*40, c*40+40). 320 thr = 32 k-chunks x 10 d-quads; each
// thread: 10 k's x 4 d's in fp32 registers. m (320 k, duplicated {m,m})
// replicated per CTA, ping-pong; gate broadcasts 40 new m's to all 8 CTAs via
// st.shared::cluster; one cluster barrier per step. u/p(t+1) prefetched into
// registers to hide L2 latency (cluster.sync flushes L1 every step).
#define R8T 320
#define DBLK 40

__global__ void __launch_bounds__(R8T, 1) __cluster_dims__(8, 1, 1)
k_recur8(const float* __restrict__ Uu) {
    __shared__ float mdup[2][2 * KP];   // [parity][2*k] = {m,m}
    __shared__ float vpf[32][DBLK];     // partial v per k-chunk
    int tid = threadIdx.x;
    unsigned cta;
    asm("mov.u32 %0, %%cluster_ctarank;" : "=r"(cta));

    int kc = tid / 10;            // 0..31
    int dq = tid - kc * 10;       // 0..9
    int k0 = kc * 10;
    int dg = (int)cta * DBLK + dq * 4;   // multiple of 4 -> aligned float4
    bool act = dg < DD;
    int dl4 = dq * 4;

    // ---- weights into registers: 10 k x 4 d as fp32 pairs ----
    unsigned long long wlo[10], whi[10];
#pragma unroll
    for (int j = 0; j < 10; j++) { wlo[j] = 0ULL; whi[j] = 0ULL; }
    if (act) {
#pragma unroll
        for (int j = 0; j < 10; j++) {
            int k = k0 + j;
            if (k < DD) {
                float4 w = *(const float4*)&Uu[(size_t)k * DD + dg];
                wlo[j] = pk64(__float_as_uint(w.x), __float_as_uint(w.y));
                whi[j] = pk64(__float_as_uint(w.z), __float_as_uint(w.w));
            }
        }
    }

    for (int i = tid; i < 2 * 2 * KP; i += R8T) ((float*)mdup)[i] = 0.f;
    __syncthreads();
    asm volatile("barrier.cluster.arrive.aligned;" ::: "memory");
    asm volatile("barrier.cluster.wait.aligned;" ::: "memory");

    // gate mapping: thread gi<40 handles global d = cta*40 + gi
    int gi = tid;
    int gd = (int)cta * DBLK + gi;
    bool gact = (gi < DBLK) && (gd < DD);
    uint32_t mbase[2];
    mbase[0] = smem_u32(&mdup[0][0]);
    mbase[1] = smem_u32(&mdup[1][0]);

    // prefetch u/p for t=0
    float un = 0.f, pn = 0.f;
    if (gact) {
        un = g_U[gd];
        pn = g_P0[gd];
    }

    for (int t = 0; t < T_STEPS; t++) {
        int par = t & 1;
        float uval = un, pval = pn;
        if (gact && t + 1 < T_STEPS) {          // prefetch next step (hides L2)
            un = g_U[(size_t)(t + 1) * DD + gd];
            pn = g_P0[(size_t)(t + 1) * DD + gd];
        }
        if (act) {
            const ulonglong2* mp = (const ulonglong2*)&mdup[par][2 * k0];
            unsigned long long acc0 = 0ULL, acc1 = 0ULL;
#pragma unroll
            for (int j = 0; j < 5; j++) {
                ulonglong2 mm = mp[j];          // {m_k,m_k},{m_k1,m_k1}
                fma2(acc0, wlo[2 * j], mm.x);
                fma2(acc1, whi[2 * j], mm.x);
                fma2(acc0, wlo[2 * j + 1], mm.y);
                fma2(acc1, whi[2 * j + 1], mm.y);
            }
            *(unsigned long long*)&vpf[kc][dl4] = acc0;
            *(unsigned long long*)&vpf[kc][dl4 + 2] = acc1;
        }
        __syncthreads();
        if (gact) {
            float v = 0.f;
#pragma unroll
            for (int c = 0; c < 32; c++) v += vpf[c][gi];
            float z = uval + v;
            float g = 1.f / (1.f + __expf(-z));
            float mold = mdup[par][2 * gd];
            float mn = mold + g * (pval - mold);
            g_Hb[(size_t)t * KP + gd] = __float2bfloat16(fmaxf(mn, 0.f));
            unsigned long long md = pk64(__float_as_uint(mn), __float_as_uint(mn));
            uint32_t loff = mbase[par ^ 1] + (uint32_t)(8 * gd);
#pragma unroll
            for (unsigned r = 0; r < 8; r++) {
                uint32_t ra;
                asm("mapa.shared::cluster.u32 %0, %1, %2;" : "=r"(ra) : "r"(loff), "r"(r));
                asm volatile("st.shared::cluster.b64 [%0], %1;" :: "r"(ra), "l"(md) : "memory");
            }
        }
        asm volatile("barrier.cluster.arrive.aligned;" ::: "memory");
        asm volatile("barrier.cluster.wait.aligned;" ::: "memory");
    }
}

// ---------------- kernel 5: logits via mma.sync bf16 ----------------
__global__ __launch_bounds__(256) void k_logits_mma(const float* __restrict__ bg,
                                                    float* __restrict__ out) {
    __shared__ __align__(16) __nv_bfloat16 As[128 * LPITCH];
    __shared__ __align__(16) __nv_bfloat16 Bs[128 * LPITCH];
    int tid = threadIdx.x;
    int wid = tid >> 5, lane = tid & 31;
    int wm = wid & 1, wn = wid >> 1;
    int v0 = blockIdx.x * 128;
    int t0 = blockIdx.y * 128;

    float acc[4][4][4];
#pragma unroll
    for (int mt = 0; mt < 4; mt++)
#pragma unroll
        for (int nt = 0; nt < 4; nt++)
#pragma unroll
            for (int r = 0; r < 4; r++) acc[mt][nt][r] = 0.f;

    uint32_t sA = smem_u32(As), sB = smem_u32(Bs);
    int lrow = lane & 15;
    int lcol = (lane >> 4) << 3;

    for (int kb = 0; kb < KP; kb += 32) {
        __syncthreads();
#pragma unroll
        for (int h = 0; h < 2; h++) {
            int c = tid + h * 256;
            int r = c >> 2, q = c & 3;
            *(uint4*)(As + r * LPITCH + q * 8) =
                *(const uint4*)&g_Hb[(size_t)(t0 + r) * KP + kb + q * 8];
            *(uint4*)(Bs + r * LPITCH + q * 8) =
                *(const uint4*)&g_Wgb[(size_t)(v0 + r) * KP + kb + q * 8];
        }
        __syncthreads();
#pragma unroll
        for (int ks = 0; ks < 32; ks += 16) {
            uint32_t af[4][4], bfr[2][4];
#pragma unroll
            for (int mt = 0; mt < 4; mt++)
                ldm_x4(af[mt],
                       sA + (uint32_t)(((wm * 64 + mt * 16 + lrow) * LPITCH + ks + lcol) * 2));
#pragma unroll
            for (int np = 0; np < 2; np++)
                ldm_x4(bfr[np],
                       sB + (uint32_t)(((wn * 32 + np * 16 + lrow) * LPITCH + ks + lcol) * 2));
#pragma unroll
            for (int mt = 0; mt < 4; mt++) {
#pragma unroll
                for (int nt = 0; nt < 4; nt++) {
                    int np = nt >> 1, sub = nt & 1;
                    mma_bf16(acc[mt][nt], af[mt], bfr[np][sub], bfr[np][sub + 2]);
                }
            }
        }
    }

    int grp = lane >> 2, qc = (lane & 3) * 2;
#pragma unroll
    for (int nt = 0; nt < 4; nt++) {
        int v = v0 + wn * 32 + nt * 8 + qc;
        if (v >= VGN) continue;
        float b0 = bg[v], b1 = bg[v + 1];
#pragma unroll
        for (int mt = 0; mt < 4; mt++) {
            int t = t0 + wm * 64 + mt * 16 + grp;
            float2 o0 = make_float2(acc[mt][nt][0] + b0, acc[mt][nt][1] + b1);
            float2 o1 = make_float2(acc[mt][nt][2] + b0, acc[mt][nt][3] + b1);
            *(float2*)&out[(size_t)t * VGN + v] = o0;
            *(float2*)&out[(size_t)(t + 8) * VGN + v] = o1;
        }
    }
}

// ---------------- kernel 6: log_softmax, online max+sum (2 passes total) -----
__global__ __launch_bounds__(512) void k_logsoftmax(float* __restrict__ out) {
    int t = blockIdx.x;
    float* row = out + (size_t)t * VGN;
    __shared__ float rm[16], rs[16];
    int tid = threadIdx.x;
    int lane = tid & 31, w = tid >> 5;

    // online max+sum in one read pass (deterministic fixed order)
    float mr = -1e30f, sr = 0.f;
    const float4* row4 = (const float4*)row;
    for (int v = tid; v < VGN / 4; v += 512) {
        float4 x = row4[v];
        float xs[4] = {x.x, x.y, x.z, x.w};
#pragma unroll
        for (int c = 0; c < 4; c++) {
            float xv = xs[c];
            if (xv <= mr) {
                sr += __expf(xv - mr);
            } else {
                sr = sr * __expf(mr - xv) + 1.f;
                mr = xv;
            }
        }
    }
#pragma unroll
    for (int o = 16; o; o >>= 1) {
        float mo = __shfl_xor_sync(~0u, mr, o);
        float so = __shfl_xor_sync(~0u, sr, o);
        float nm = fmaxf(mr, mo);
        sr = sr * __expf(mr - nm) + so * __expf(mo - nm);
        mr = nm;
    }
    if (lane == 0) { rm[w] = mr; rs[w] = sr; }
    __syncthreads();
    if (tid == 0) {
        float M = rm[0], S = rs[0];
#pragma unroll
        for (int i = 1; i < 16; i++) {
            float nm = fmaxf(M, rm[i]);
            S = S * __expf(M - nm) + rs[i] * __expf(rm[i] - nm);
            M = nm;
        }
        rm[0] = M + logf(S);
    }
    __syncthreads();
    float lse = rm[0];

    float4* row4w = (float4*)row;
    for (int v = tid; v < VGN / 4; v += 512) {
        float4 x = row4w[v];
        x.x -= lse; x.y -= lse; x.z -= lse; x.w -= lse;
        row4w[v] = x;
    }
}

// ---------------- tail zero (second ref output = zeros) ----------------
__global__ void k_zero(float* out, size_t start, size_t n) {
    size_t i = (size_t)blockIdx.x * blockDim.x + threadIdx.x;
    if (i < n) out[start + i] = 0.f;
}

extern "C" void kernel_launch(void* const* d_in, const int* in_sizes, int n_in,
                              void* d_out, int out_size) {
    const int*   xidx  = (const int*)d_in[0];
    const int*   esrc  = (const int*)d_in[1];
    const int*   edst  = (const int*)d_in[2];
    const float* X     = (const float*)d_in[3];
    const float* convW = (const float*)d_in[4];
    const float* W0    = (const float*)d_in[5];
    const float* Wu    = (const float*)d_in[6];
    const float* Uu    = (const float*)d_in[7];
    const float* Wg    = (const float*)d_in[8];
    const float* bg    = (const float*)d_in[9];
    float* out = (float*)d_out;

    k_gather<<<T_STEPS, 256>>>(xidx, X);
    {
        size_t nw = ((size_t)VP * KP) / 2;
        k_cvtW<<<(unsigned)((nw + 255) / 256), 256>>>(Wg);
    }
    k_padH<<<(T_STEPS * 20 + 255) / 256, 256>>>();
    k_trWu<<<dim3(KFLAT / 32, NP / 32), 1024>>>(Wu);
    k_trWcat<<<dim3(KY / 32, NP / 32), 1024>>>(convW, W0);
    k_coefY<<<T_STEPS, 128>>>(esrc, edst);
    k_tcgemm<<<dim3(3, 4, UKS), 256>>>(0);   // U partials
    k_tcgemm<<<dim3(3, 4, PKS), 256>>>(1);   // P partials
    k_reduce2<<<(TD + 255) / 256, 256>>>();
    k_recur8<<<8, R8T>>>(Uu);
    k_logits_mma<<<dim3(VP / 128, T_STEPS / 128), 256>>>(bg, out);
    k_logsoftmax<<<T_STEPS, 512>>>(out);

    size_t used = (size_t)T_STEPS * VGN;
    if ((size_t)out_size > used) {
        size_t n = (size_t)out_size - used;
        k_zero<<<(unsigned)((n + 255) / 256), 256>>>(out, used, n);
    }
}